// round 7
// baseline (speedup 1.0000x reference)
#include <cuda_runtime.h>
#include <cuda_bf16.h>
#include <cuda_fp16.h>
#include <math.h>
#include <stdint.h>

#define BATCH 4
#define SEQ   2048
#define DIM   1024
#define MTOT  (BATCH * SEQ)   // 8192

// ======================= device scratch (no runtime alloc) =======================
__device__ __align__(128) __nv_bfloat16 g_xhi[(size_t)MTOT * DIM];
__device__ __align__(128) __nv_bfloat16 g_xlo[(size_t)MTOT * DIM];
__device__ __align__(128) __nv_bfloat16 g_whi[3][(size_t)DIM * DIM];   // [din][dout]
__device__ __align__(128) __nv_bfloat16 g_wlo[3][(size_t)DIM * DIM];
__device__ __align__(128) __nv_bfloat16 g_qhi[(size_t)MTOT * DIM];
__device__ __align__(128) __nv_bfloat16 g_qlo[(size_t)MTOT * DIM];
__device__ __align__(128) __nv_bfloat16 g_khi[(size_t)MTOT * DIM];
__device__ __align__(128) __nv_bfloat16 g_klo[(size_t)MTOT * DIM];
__device__ __align__(128) __half        g_vh[(size_t)MTOT * DIM];         // fp16 V
__device__ __align__(128) __half        g_phi[(size_t)BATCH * SEQ * SEQ]; // unnorm probs (fp16)
__device__ __align__(128) float         g_partial[BATCH][SEQ / 128][SEQ]; // rowsum partials

// ======================= PTX helpers (arch-agnostic, sm_80-era) =======================
__device__ __forceinline__ uint32_t smem_u32(const void* p) {
    uint32_t a;
    asm("{ .reg .u64 t; cvta.to.shared.u64 t, %1; cvt.u32.u64 %0, t; }" : "=r"(a) : "l"(p));
    return a;
}
__device__ __forceinline__ void cp16(uint32_t dst, const void* src) {
    asm volatile("cp.async.cg.shared.global [%0], [%1], 16;" :: "r"(dst), "l"(src));
}
__device__ __forceinline__ void cp_commit() { asm volatile("cp.async.commit_group;"); }
template<int N>
__device__ __forceinline__ void cp_wait() { asm volatile("cp.async.wait_group %0;" :: "n"(N)); }

__device__ __forceinline__ void ldsm4(uint32_t* r, uint32_t a) {
    asm volatile("ldmatrix.sync.aligned.m8n8.x4.shared.b16 {%0,%1,%2,%3}, [%4];"
                 : "=r"(r[0]), "=r"(r[1]), "=r"(r[2]), "=r"(r[3]) : "r"(a));
}
__device__ __forceinline__ void ldsm4t(uint32_t* r, uint32_t a) {
    asm volatile("ldmatrix.sync.aligned.m8n8.x4.trans.shared.b16 {%0,%1,%2,%3}, [%4];"
                 : "=r"(r[0]), "=r"(r[1]), "=r"(r[2]), "=r"(r[3]) : "r"(a));
}
__device__ __forceinline__ void mma_bf16(float* c, const uint32_t* a, const uint32_t* b) {
    asm volatile(
        "mma.sync.aligned.m16n8k16.row.col.f32.bf16.bf16.f32 "
        "{%0,%1,%2,%3},{%4,%5,%6,%7},{%8,%9},{%0,%1,%2,%3};"
        : "+f"(c[0]), "+f"(c[1]), "+f"(c[2]), "+f"(c[3])
        : "r"(a[0]), "r"(a[1]), "r"(a[2]), "r"(a[3]), "r"(b[0]), "r"(b[1]));
}
__device__ __forceinline__ void mma_f16(float* c, const uint32_t* a, const uint32_t* b) {
    asm volatile(
        "mma.sync.aligned.m16n8k16.row.col.f32.f16.f16.f32 "
        "{%0,%1,%2,%3},{%4,%5,%6,%7},{%8,%9},{%0,%1,%2,%3};"
        : "+f"(c[0]), "+f"(c[1]), "+f"(c[2]), "+f"(c[3])
        : "r"(a[0]), "r"(a[1]), "r"(a[2]), "r"(a[3]), "r"(b[0]), "r"(b[1]));
}

// ======================= smem layouts =======================
// gemm3 stage: Ahi/Alo (AROWS x 32 halves, stride 80B) + Bhi/Blo (BT each)
//   AROWS=128: A part 10240B; AROWS=256: 20480B. BT: 8704 (KN) / 10240 (NK)
// pv (1-term) stage: Ahi(10240) + Bhi(8704) = 18944; 2 stages + 512B rsinv.
#define STAGE1_B    18944
#define SMEM1_BYTES (2 * STAGE1_B + 512)   // 38400

__device__ __forceinline__ void st_split2_bf16(__nv_bfloat16* hi, __nv_bfloat16* lo,
                                               size_t off, float f0, float f1) {
    __nv_bfloat16 h0 = __float2bfloat16(f0), h1 = __float2bfloat16(f1);
    __nv_bfloat16 l0 = __float2bfloat16(f0 - __bfloat162float(h0));
    __nv_bfloat16 l1 = __float2bfloat16(f1 - __bfloat162float(h1));
    uint32_t hp = (uint32_t)__bfloat16_as_ushort(h0) | ((uint32_t)__bfloat16_as_ushort(h1) << 16);
    uint32_t lp = (uint32_t)__bfloat16_as_ushort(l0) | ((uint32_t)__bfloat16_as_ushort(l1) << 16);
    *reinterpret_cast<uint32_t*>(hi + off) = hp;
    *reinterpret_cast<uint32_t*>(lo + off) = lp;
}

// ======================= 3-term split-bf16 GEMM, 2-stage, 1 sync/chunk =======================
// CTA tile: AROWS x 128, T = 2*AROWS threads, warp tile 64x32.
// BKN=true : B stored [k][n] row-major (ldb = n-stride), uses ldmatrix.trans
// BKN=false: B stored [n][k] row-major (ldb = k-stride), uses ldmatrix
template<int AROWS, int T, bool BKN>
__device__ __forceinline__ void gemm3_bf16(
    const __nv_bfloat16* __restrict__ ahi, const __nv_bfloat16* __restrict__ alo, int lda,
    const __nv_bfloat16* __restrict__ bhi, const __nv_bfloat16* __restrict__ blo, int ldb,
    int nchunks, float (&acc)[4][4][4])
{
    extern __shared__ char smem[];
    const uint32_t sb = smem_u32(smem);
    const int tid = threadIdx.x;
    const int lane = tid & 31, warp = tid >> 5;
    const int wm = warp >> 2, wn = warp & 3;
    constexpr int APART = AROWS * 80;                 // bytes per A half-tile
    constexpr int BT = BKN ? 8704 : 10240;
    constexpr int STAGE = 2 * APART + 2 * BT;

#pragma unroll
    for (int mi = 0; mi < 4; mi++)
#pragma unroll
        for (int ni = 0; ni < 4; ni++)
#pragma unroll
            for (int k = 0; k < 4; k++) acc[mi][ni][k] = 0.f;

    auto load_chunk = [&](int s, int c) {
        const uint32_t base = sb + (uint32_t)s * STAGE;
        const uint32_t ah = base, al = base + APART;
        const uint32_t bh = base + 2 * APART, bl = base + 2 * APART + BT;
#pragma unroll
        for (int i = tid; i < AROWS * 4; i += T) {    // A: AROWS rows x 4 vec8
            int row = i >> 2, cc = i & 3;
            size_t go = (size_t)row * lda + c * 32 + cc * 8;
            uint32_t so = (uint32_t)row * 80u + (uint32_t)cc * 16u;
            cp16(ah + so, ahi + go);
            cp16(al + so, alo + go);
        }
#pragma unroll
        for (int i = tid; i < 512; i += T) {          // B: 512 vec8
            if (BKN) {
                int row = i >> 4, cc = i & 15;
                size_t go = (size_t)(c * 32 + row) * ldb + cc * 8;
                uint32_t so = (uint32_t)row * 272u + (uint32_t)cc * 16u;
                cp16(bh + so, bhi + go);
                cp16(bl + so, blo + go);
            } else {
                int row = i >> 2, cc = i & 3;
                size_t go = (size_t)row * ldb + c * 32 + cc * 8;
                uint32_t so = (uint32_t)row * 80u + (uint32_t)cc * 16u;
                cp16(bh + so, bhi + go);
                cp16(bl + so, blo + go);
            }
        }
        cp_commit();
    };

    load_chunk(0, 0);
    for (int c = 0; c < nchunks; ++c) {
        cp_wait<0>();
        __syncthreads();
        if (c + 1 < nchunks) load_chunk((c + 1) & 1, c + 1);

        const int buf = c & 1;
        const uint32_t base = sb + (uint32_t)buf * STAGE;
        const uint32_t ah = base, al = base + APART;
        const uint32_t bh = base + 2 * APART, bl = base + 2 * APART + BT;

#pragma unroll
        for (int ks = 0; ks < 2; ++ks) {
            uint32_t Ah[4][4], Al[4][4], Bh[4][2], Bl[4][2];
            const uint32_t ao = (uint32_t)(wm * 64 + (lane & 15)) * 80u
                              + (uint32_t)(ks * 16 + (lane >> 4) * 8) * 2u;
#pragma unroll
            for (int mi = 0; mi < 4; mi++) {
                ldsm4(Ah[mi], ah + ao + (uint32_t)(mi * 16) * 80u);
                ldsm4(Al[mi], al + ao + (uint32_t)(mi * 16) * 80u);
            }
            if (BKN) {
                const uint32_t brow = (uint32_t)(ks * 16 + (lane & 15));
#pragma unroll
                for (int p = 0; p < 2; p++) {
                    const uint32_t bo = brow * 272u
                        + (uint32_t)(wn * 32 + p * 16 + (lane >> 4) * 8) * 2u;
                    uint32_t r[4];
                    ldsm4t(r, bh + bo);
                    Bh[2*p][0] = r[0]; Bh[2*p][1] = r[1];
                    Bh[2*p+1][0] = r[2]; Bh[2*p+1][1] = r[3];
                    ldsm4t(r, bl + bo);
                    Bl[2*p][0] = r[0]; Bl[2*p][1] = r[1];
                    Bl[2*p+1][0] = r[2]; Bl[2*p+1][1] = r[3];
                }
            } else {
                const uint32_t bcol2 = (uint32_t)(ks * 16 + ((lane >> 3) & 1) * 8) * 2u;
#pragma unroll
                for (int p = 0; p < 2; p++) {
                    const uint32_t brow = (uint32_t)(wn * 32 + p * 16 + (lane & 7) + ((lane >> 4) << 3));
                    const uint32_t bo = brow * 80u + bcol2;
                    uint32_t r[4];
                    ldsm4(r, bh + bo);
                    Bh[2*p][0] = r[0]; Bh[2*p][1] = r[1];
                    Bh[2*p+1][0] = r[2]; Bh[2*p+1][1] = r[3];
                    ldsm4(r, bl + bo);
                    Bl[2*p][0] = r[0]; Bl[2*p][1] = r[1];
                    Bl[2*p+1][0] = r[2]; Bl[2*p+1][1] = r[3];
                }
            }
#pragma unroll
            for (int mi = 0; mi < 4; mi++)
#pragma unroll
                for (int ni = 0; ni < 4; ni++) {
                    mma_bf16(acc[mi][ni], Ah[mi], Bh[ni]);
                    mma_bf16(acc[mi][ni], Ah[mi], Bl[ni]);
                    mma_bf16(acc[mi][ni], Al[mi], Bh[ni]);
                }
        }
    }
    __syncthreads();
}

// ======================= 1-term fp16 GEMM: C = Ahi * Bhi, B in [k][n], 2-stage =======================
__device__ __forceinline__ void gemm1_f16(
    const __half* __restrict__ ahi, int lda,
    const __half* __restrict__ bhi, int ldb,
    int nchunks, float (&acc)[4][4][4])
{
    extern __shared__ char smem[];
    const uint32_t sb = smem_u32(smem);
    const int tid = threadIdx.x;
    const int lane = tid & 31, warp = tid >> 5;
    const int wm = warp >> 2, wn = warp & 3;

#pragma unroll
    for (int mi = 0; mi < 4; mi++)
#pragma unroll
        for (int ni = 0; ni < 4; ni++)
#pragma unroll
            for (int k = 0; k < 4; k++) acc[mi][ni][k] = 0.f;

    auto load_chunk = [&](int s, int c) {
        const uint32_t base = sb + (uint32_t)s * STAGE1_B;
        const uint32_t ah = base, bh = base + 10240u;
        int i = tid;
#pragma unroll
        for (int j = 0; j < 2; j++, i += 256) {
            {
                int row = i >> 2, cc = i & 3;
                size_t go = (size_t)row * lda + c * 32 + cc * 8;
                uint32_t so = (uint32_t)row * 80u + (uint32_t)cc * 16u;
                cp16(ah + so, ahi + go);
            }
            {
                int row = i >> 4, cc = i & 15;
                size_t go = (size_t)(c * 32 + row) * ldb + cc * 8;
                uint32_t so = (uint32_t)row * 272u + (uint32_t)cc * 16u;
                cp16(bh + so, bhi + go);
            }
        }
        cp_commit();
    };

    load_chunk(0, 0);
    for (int c = 0; c < nchunks; ++c) {
        cp_wait<0>();
        __syncthreads();
        if (c + 1 < nchunks) load_chunk((c + 1) & 1, c + 1);

        const int buf = c & 1;
        const uint32_t base = sb + (uint32_t)buf * STAGE1_B;
        const uint32_t ah = base, bh = base + 10240u;

#pragma unroll
        for (int ks = 0; ks < 2; ++ks) {
            uint32_t Ah[4][4], Bh[4][2];
            const uint32_t ao = (uint32_t)(wm * 64 + (lane & 15)) * 80u
                              + (uint32_t)(ks * 16 + (lane >> 4) * 8) * 2u;
#pragma unroll
            for (int mi = 0; mi < 4; mi++)
                ldsm4(Ah[mi], ah + ao + (uint32_t)(mi * 16) * 80u);
            const uint32_t brow = (uint32_t)(ks * 16 + (lane & 15));
#pragma unroll
            for (int p = 0; p < 2; p++) {
                const uint32_t bo = brow * 272u
                    + (uint32_t)(wn * 32 + p * 16 + (lane >> 4) * 8) * 2u;
                uint32_t r[4];
                ldsm4t(r, bh + bo);
                Bh[2*p][0] = r[0]; Bh[2*p][1] = r[1];
                Bh[2*p+1][0] = r[2]; Bh[2*p+1][1] = r[3];
            }
#pragma unroll
            for (int mi = 0; mi < 4; mi++)
#pragma unroll
                for (int ni = 0; ni < 4; ni++)
                    mma_f16(acc[mi][ni], Ah[mi], Bh[ni]);
        }
    }
    __syncthreads();
}

// ======================= kernel: split fp32 -> bf16 hi/lo (x + Wq + Wk + Wv) =======================
#define XN ((size_t)MTOT * DIM)          // 8388608
#define WN ((size_t)DIM * DIM)           // 1048576
__global__ __launch_bounds__(256) void split_all(const float* __restrict__ x,
                                                 const float* __restrict__ wq,
                                                 const float* __restrict__ wk,
                                                 const float* __restrict__ wv) {
    size_t i = ((size_t)blockIdx.x * 256 + threadIdx.x) * 4;
    const float* src;
    __nv_bfloat16 *hi, *lo;
    size_t off;
    if (i < XN) { src = x; off = i; hi = g_xhi; lo = g_xlo; }
    else {
        size_t j = i - XN;
        int w = (int)(j / WN);
        off = j - (size_t)w * WN;
        src = (w == 0) ? wq : (w == 1) ? wk : wv;
        hi = g_whi[w]; lo = g_wlo[w];
    }
    float4 v = *reinterpret_cast<const float4*>(src + off);
    float f[4] = {v.x, v.y, v.z, v.w};
    uint32_t hp[2], lp[2];
#pragma unroll
    for (int j = 0; j < 2; j++) {
        __nv_bfloat16 h0 = __float2bfloat16(f[2*j]),   h1 = __float2bfloat16(f[2*j+1]);
        __nv_bfloat16 l0 = __float2bfloat16(f[2*j]   - __bfloat162float(h0));
        __nv_bfloat16 l1 = __float2bfloat16(f[2*j+1] - __bfloat162float(h1));
        hp[j] = (uint32_t)__bfloat16_as_ushort(h0) | ((uint32_t)__bfloat16_as_ushort(h1) << 16);
        lp[j] = (uint32_t)__bfloat16_as_ushort(l0) | ((uint32_t)__bfloat16_as_ushort(l1) << 16);
    }
    *reinterpret_cast<uint2*>(hi + off) = make_uint2(hp[0], hp[1]);
    *reinterpret_cast<uint2*>(lo + off) = make_uint2(lp[0], lp[1]);
}

// ======================= kernel: QKV projection (256x128 tile, 512 threads) =======================
#define SMEM3Q_BYTES (2 * (2 * 256 * 80 + 2 * 8704))   // 116736
__global__ __launch_bounds__(512) void qkv_gemm() {
    const int z = blockIdx.z, m0 = blockIdx.y * 256, n0 = blockIdx.x * 128;
    float acc[4][4][4];
    gemm3_bf16<256, 512, true>(g_xhi + (size_t)m0 * DIM, g_xlo + (size_t)m0 * DIM, DIM,
                               g_whi[z] + n0, g_wlo[z] + n0, DIM, DIM / 32, acc);
    const int lane = threadIdx.x & 31, warp = threadIdx.x >> 5;
    const int g = lane >> 2, t = lane & 3, wm = warp >> 2, wn = warp & 3;
#pragma unroll
    for (int mi = 0; mi < 4; mi++) {
        const int r0 = m0 + wm * 64 + mi * 16 + g;
#pragma unroll
        for (int ni = 0; ni < 4; ni++) {
            const int cc = n0 + wn * 32 + ni * 8 + 2 * t;
            if (z == 2) {
                __half h0 = __float2half_rn(acc[mi][ni][0]);
                __half h1 = __float2half_rn(acc[mi][ni][1]);
                __half h2 = __float2half_rn(acc[mi][ni][2]);
                __half h3 = __float2half_rn(acc[mi][ni][3]);
                *reinterpret_cast<uint32_t*>(g_vh + (size_t)r0 * DIM + cc) =
                    (uint32_t)__half_as_ushort(h0) | ((uint32_t)__half_as_ushort(h1) << 16);
                *reinterpret_cast<uint32_t*>(g_vh + (size_t)(r0 + 8) * DIM + cc) =
                    (uint32_t)__half_as_ushort(h2) | ((uint32_t)__half_as_ushort(h3) << 16);
            } else {
                __nv_bfloat16* oh = (z == 0) ? g_qhi : g_khi;
                __nv_bfloat16* ol = (z == 0) ? g_qlo : g_klo;
                st_split2_bf16(oh, ol, (size_t)r0 * DIM + cc,       acc[mi][ni][0], acc[mi][ni][1]);
                st_split2_bf16(oh, ol, (size_t)(r0 + 8) * DIM + cc, acc[mi][ni][2], acc[mi][ni][3]);
            }
        }
    }
}

// ======================= kernel: fused scores = exp(QK^T*scale) (causal, triangular grid) =======================
#define SMEM3S_BYTES (2 * (2 * 128 * 80 + 2 * 10240))   // 81920
__global__ __launch_bounds__(256) void scores_gemm() {
    extern __shared__ char smem[];
    // triangular decode: blockIdx.x in [0,136) -> (ty >= tx)
    const int li = blockIdx.x;
    int ty = (int)((sqrtf(8.f * li + 1.f) - 1.f) * 0.5f);
    while ((ty + 1) * (ty + 2) / 2 <= li) ty++;
    while (ty * (ty + 1) / 2 > li) ty--;
    const int tx = li - ty * (ty + 1) / 2;
    const int b = blockIdx.z, q0 = ty * 128, k0 = tx * 128;
    const size_t boff = (size_t)b * SEQ * DIM;
    float acc[4][4][4];
    gemm3_bf16<128, 256, false>(g_qhi + boff + (size_t)q0 * DIM, g_qlo + boff + (size_t)q0 * DIM, DIM,
                                g_khi + boff + (size_t)k0 * DIM, g_klo + boff + (size_t)k0 * DIM, DIM,
                                DIM / 32, acc);
    const bool diag = (tx == ty);
    __half* ph = g_phi + (size_t)b * SEQ * SEQ;
    const int lane = threadIdx.x & 31, warp = threadIdx.x >> 5;
    const int g = lane >> 2, t = lane & 3, wm = warp >> 2, wn = warp & 3;
    const float scale = 0.03125f;

    float* red = reinterpret_cast<float*>(smem);
    float rs0[4], rs1[4];
#pragma unroll
    for (int mi = 0; mi < 4; mi++) { rs0[mi] = 0.f; rs1[mi] = 0.f; }

#pragma unroll
    for (int mi = 0; mi < 4; mi++) {
        const int r0 = q0 + wm * 64 + mi * 16 + g;
#pragma unroll
        for (int ni = 0; ni < 4; ni++) {
            const int cc = k0 + wn * 32 + ni * 8 + 2 * t;
            float e0 = __expf(acc[mi][ni][0] * scale);
            float e1 = __expf(acc[mi][ni][1] * scale);
            float e2 = __expf(acc[mi][ni][2] * scale);
            float e3 = __expf(acc[mi][ni][3] * scale);
            if (diag) {
                if (cc     > r0)     e0 = 0.f;
                if (cc + 1 > r0)     e1 = 0.f;
                if (cc     > r0 + 8) e2 = 0.f;
                if (cc + 1 > r0 + 8) e3 = 0.f;
            }
            __half p0 = __float2half_rn(e0), p1 = __float2half_rn(e1);
            __half p2 = __float2half_rn(e2), p3 = __float2half_rn(e3);
            *reinterpret_cast<uint32_t*>(ph + (size_t)r0 * SEQ + cc) =
                (uint32_t)__half_as_ushort(p0) | ((uint32_t)__half_as_ushort(p1) << 16);
            *reinterpret_cast<uint32_t*>(ph + (size_t)(r0 + 8) * SEQ + cc) =
                (uint32_t)__half_as_ushort(p2) | ((uint32_t)__half_as_ushort(p3) << 16);
            rs0[mi] += e0 + e1;
            rs1[mi] += e2 + e3;
        }
    }
#pragma unroll
    for (int mi = 0; mi < 4; mi++) {
        float s0 = rs0[mi], s1 = rs1[mi];
        s0 += __shfl_xor_sync(0xFFFFFFFFu, s0, 1);
        s0 += __shfl_xor_sync(0xFFFFFFFFu, s0, 2);
        s1 += __shfl_xor_sync(0xFFFFFFFFu, s1, 1);
        s1 += __shfl_xor_sync(0xFFFFFFFFu, s1, 2);
        if (t == 0) {
            const int lr = wm * 64 + mi * 16 + g;
            red[wn * 128 + lr]     = s0;
            red[wn * 128 + lr + 8] = s1;
        }
    }
    __syncthreads();
    if (threadIdx.x < 128) {
        float tot = red[threadIdx.x] + red[128 + threadIdx.x]
                  + red[256 + threadIdx.x] + red[384 + threadIdx.x];
        g_partial[b][tx][q0 + threadIdx.x] = tot;
    }
}

// ======================= kernel: O = (P @ V) * rsuminv (rowsum fused in prologue) =======================
__global__ __launch_bounds__(256) void pv_gemm(float* __restrict__ outp) {
    extern __shared__ char smem[];
    const int b = blockIdx.z, q0 = blockIdx.y * 128, n0 = blockIdx.x * 128;

    // prologue: per-row 1/rowsum into smem beyond the pipeline buffers
    float* rsinv = reinterpret_cast<float*>(smem + 2 * STAGE1_B);
    if (threadIdx.x < 128) {
        const int q = q0 + threadIdx.x;
        const int nt = (q0 >> 7) + 1;
        float s = 0.f;
        for (int j = 0; j < nt; j++) s += g_partial[b][j][q];
        rsinv[threadIdx.x] = 1.f / s;
    }

    float acc[4][4][4];
    gemm1_f16(g_phi + (size_t)b * SEQ * SEQ + (size_t)q0 * SEQ, SEQ,
              g_vh + (size_t)b * SEQ * DIM + n0, DIM,
              (q0 + 128) / 32, acc);   // ends with __syncthreads -> rsinv visible
    float* out = outp + (size_t)b * SEQ * DIM;
    const int lane = threadIdx.x & 31, warp = threadIdx.x >> 5;
    const int g = lane >> 2, t = lane & 3, wm = warp >> 2, wn = warp & 3;
#pragma unroll
    for (int mi = 0; mi < 4; mi++) {
        const int lr = wm * 64 + mi * 16 + g;
        const int r0 = q0 + lr;
        const float i0 = rsinv[lr], i1 = rsinv[lr + 8];
#pragma unroll
        for (int ni = 0; ni < 4; ni++) {
            const int cc = n0 + wn * 32 + ni * 8 + 2 * t;
            *reinterpret_cast<float2*>(out + (size_t)r0 * DIM + cc) =
                make_float2(acc[mi][ni][0] * i0, acc[mi][ni][1] * i0);
            *reinterpret_cast<float2*>(out + (size_t)(r0 + 8) * DIM + cc) =
                make_float2(acc[mi][ni][2] * i1, acc[mi][ni][3] * i1);
        }
    }
}

// ======================= launch =======================
extern "C" void kernel_launch(void* const* d_in, const int* in_sizes, int n_in,
                              void* d_out, int out_size) {
    const float* x  = (const float*)d_in[0];
    const float* Wq = (const float*)d_in[1];
    const float* Wk = (const float*)d_in[2];
    const float* Wv = (const float*)d_in[3];
    float* out = (float*)d_out;

    cudaFuncSetAttribute(qkv_gemm,    cudaFuncAttributeMaxDynamicSharedMemorySize, SMEM3Q_BYTES);
    cudaFuncSetAttribute(scores_gemm, cudaFuncAttributeMaxDynamicSharedMemorySize, SMEM3S_BYTES);
    cudaFuncSetAttribute(pv_gemm,     cudaFuncAttributeMaxDynamicSharedMemorySize, SMEM1_BYTES);

    const size_t total = XN + 3 * WN;
    split_all<<<(unsigned)(total / 1024), 256>>>(x, Wq, Wk, Wv);

    qkv_gemm<<<dim3(DIM / 128, MTOT / 256, 3), 512, SMEM3Q_BYTES>>>();
    scores_gemm<<<dim3(136, 1, BATCH), 256, SMEM3S_BYTES>>>();
    pv_gemm<<<dim3(DIM / 128, SEQ / 128, BATCH), 256, SMEM1_BYTES>>>(out);
}

// round 8
// speedup vs baseline: 1.0205x; 1.0205x over previous
#include <cuda_runtime.h>
#include <cuda_bf16.h>
#include <cuda_fp16.h>
#include <math.h>
#include <stdint.h>

#define BATCH 4
#define SEQ   2048
#define DIM   1024
#define MTOT  (BATCH * SEQ)   // 8192

// ======================= device scratch (no runtime alloc) =======================
__device__ __align__(128) __nv_bfloat16 g_xhi[(size_t)MTOT * DIM];
__device__ __align__(128) __nv_bfloat16 g_xlo[(size_t)MTOT * DIM];
__device__ __align__(128) __nv_bfloat16 g_whi[3][(size_t)DIM * DIM];   // [din][dout]
__device__ __align__(128) __nv_bfloat16 g_wlo[3][(size_t)DIM * DIM];
__device__ __align__(128) __nv_bfloat16 g_qhi[(size_t)MTOT * DIM];
__device__ __align__(128) __nv_bfloat16 g_qlo[(size_t)MTOT * DIM];
__device__ __align__(128) __nv_bfloat16 g_khi[(size_t)MTOT * DIM];
__device__ __align__(128) __nv_bfloat16 g_klo[(size_t)MTOT * DIM];
__device__ __align__(128) __half        g_vh[(size_t)MTOT * DIM];         // fp16 V
__device__ __align__(128) __half        g_phi[(size_t)BATCH * SEQ * SEQ]; // unnorm probs (fp16)
__device__ __align__(128) float         g_partial[BATCH][SEQ / 128][SEQ]; // rowsum partials

// ======================= PTX helpers (arch-agnostic, sm_80-era) =======================
__device__ __forceinline__ uint32_t smem_u32(const void* p) {
    uint32_t a;
    asm("{ .reg .u64 t; cvta.to.shared.u64 t, %1; cvt.u32.u64 %0, t; }" : "=r"(a) : "l"(p));
    return a;
}
__device__ __forceinline__ void cp16(uint32_t dst, const void* src) {
    asm volatile("cp.async.cg.shared.global [%0], [%1], 16;" :: "r"(dst), "l"(src));
}
__device__ __forceinline__ void cp_commit() { asm volatile("cp.async.commit_group;"); }
template<int N>
__device__ __forceinline__ void cp_wait() { asm volatile("cp.async.wait_group %0;" :: "n"(N)); }

__device__ __forceinline__ void ldsm4(uint32_t* r, uint32_t a) {
    asm volatile("ldmatrix.sync.aligned.m8n8.x4.shared.b16 {%0,%1,%2,%3}, [%4];"
                 : "=r"(r[0]), "=r"(r[1]), "=r"(r[2]), "=r"(r[3]) : "r"(a));
}
__device__ __forceinline__ void ldsm4t(uint32_t* r, uint32_t a) {
    asm volatile("ldmatrix.sync.aligned.m8n8.x4.trans.shared.b16 {%0,%1,%2,%3}, [%4];"
                 : "=r"(r[0]), "=r"(r[1]), "=r"(r[2]), "=r"(r[3]) : "r"(a));
}
__device__ __forceinline__ void mma_bf16(float* c, const uint32_t* a, const uint32_t* b) {
    asm volatile(
        "mma.sync.aligned.m16n8k16.row.col.f32.bf16.bf16.f32 "
        "{%0,%1,%2,%3},{%4,%5,%6,%7},{%8,%9},{%0,%1,%2,%3};"
        : "+f"(c[0]), "+f"(c[1]), "+f"(c[2]), "+f"(c[3])
        : "r"(a[0]), "r"(a[1]), "r"(a[2]), "r"(a[3]), "r"(b[0]), "r"(b[1]));
}
__device__ __forceinline__ void mma_f16(float* c, const uint32_t* a, const uint32_t* b) {
    asm volatile(
        "mma.sync.aligned.m16n8k16.row.col.f32.f16.f16.f32 "
        "{%0,%1,%2,%3},{%4,%5,%6,%7},{%8,%9},{%0,%1,%2,%3};"
        : "+f"(c[0]), "+f"(c[1]), "+f"(c[2]), "+f"(c[3])
        : "r"(a[0]), "r"(a[1]), "r"(a[2]), "r"(a[3]), "r"(b[0]), "r"(b[1]));
}

// ======================= smem layouts =======================
// gemm3 stage (128x128 tile): Ahi/Alo (128x32 halves, stride 80B = 10240B each)
//   + Bhi/Blo (BT each); BT = 8704 (KN) / 10240 (NK).
//   KN stage = 37888 -> 2 stages 75776 (2 CTAs/SM); NK stage = 40960 -> 81920 (2 CTAs/SM).
// pv (1-term) stage: Ahi(10240) + Bhi(8704) = 18944; 2 stages + 512B rsinv = 38400.
#define STAGE1_B    18944
#define SMEM1_BYTES (2 * STAGE1_B + 512)   // 38400

__device__ __forceinline__ void st_split2_bf16(__nv_bfloat16* hi, __nv_bfloat16* lo,
                                               size_t off, float f0, float f1) {
    __nv_bfloat16 h0 = __float2bfloat16(f0), h1 = __float2bfloat16(f1);
    __nv_bfloat16 l0 = __float2bfloat16(f0 - __bfloat162float(h0));
    __nv_bfloat16 l1 = __float2bfloat16(f1 - __bfloat162float(h1));
    uint32_t hp = (uint32_t)__bfloat16_as_ushort(h0) | ((uint32_t)__bfloat16_as_ushort(h1) << 16);
    uint32_t lp = (uint32_t)__bfloat16_as_ushort(l0) | ((uint32_t)__bfloat16_as_ushort(l1) << 16);
    *reinterpret_cast<uint32_t*>(hi + off) = hp;
    *reinterpret_cast<uint32_t*>(lo + off) = lp;
}

// ======================= 3-term split-bf16 GEMM (128x128 tile, 256 thr, 2-stage, 1 sync/chunk) =======================
// BKN=true : B stored [k][n] row-major (ldb = n-stride), uses ldmatrix.trans
// BKN=false: B stored [n][k] row-major (ldb = k-stride), uses ldmatrix
template<bool BKN>
__device__ __forceinline__ void gemm3_bf16(
    const __nv_bfloat16* __restrict__ ahi, const __nv_bfloat16* __restrict__ alo, int lda,
    const __nv_bfloat16* __restrict__ bhi, const __nv_bfloat16* __restrict__ blo, int ldb,
    int nchunks, float (&acc)[4][4][4])
{
    extern __shared__ char smem[];
    const uint32_t sb = smem_u32(smem);
    const int tid = threadIdx.x;
    const int lane = tid & 31, warp = tid >> 5;
    const int wm = warp >> 2, wn = warp & 3;
    constexpr int BT = BKN ? 8704 : 10240;
    constexpr int STAGE = 20480 + 2 * BT;

#pragma unroll
    for (int mi = 0; mi < 4; mi++)
#pragma unroll
        for (int ni = 0; ni < 4; ni++)
#pragma unroll
            for (int k = 0; k < 4; k++) acc[mi][ni][k] = 0.f;

    auto load_chunk = [&](int s, int c) {
        const uint32_t base = sb + (uint32_t)s * STAGE;
        const uint32_t ah = base, al = base + 10240u;
        const uint32_t bh = base + 20480u, bl = base + 20480u + (uint32_t)BT;
        int i = tid;
#pragma unroll
        for (int j = 0; j < 2; j++, i += 256) {
            {
                int row = i >> 2, cc = i & 3;
                size_t go = (size_t)row * lda + c * 32 + cc * 8;
                uint32_t so = (uint32_t)row * 80u + (uint32_t)cc * 16u;
                cp16(ah + so, ahi + go);
                cp16(al + so, alo + go);
            }
            if (BKN) {
                int row = i >> 4, cc = i & 15;
                size_t go = (size_t)(c * 32 + row) * ldb + cc * 8;
                uint32_t so = (uint32_t)row * 272u + (uint32_t)cc * 16u;
                cp16(bh + so, bhi + go);
                cp16(bl + so, blo + go);
            } else {
                int row = i >> 2, cc = i & 3;
                size_t go = (size_t)row * ldb + c * 32 + cc * 8;
                uint32_t so = (uint32_t)row * 80u + (uint32_t)cc * 16u;
                cp16(bh + so, bhi + go);
                cp16(bl + so, blo + go);
            }
        }
        cp_commit();
    };

    load_chunk(0, 0);
    for (int c = 0; c < nchunks; ++c) {
        cp_wait<0>();          // only chunk c's group outstanding
        __syncthreads();       // data visible + all warps done with chunk c-1
        if (c + 1 < nchunks) load_chunk((c + 1) & 1, c + 1);

        const int buf = c & 1;
        const uint32_t base = sb + (uint32_t)buf * STAGE;
        const uint32_t ah = base, al = base + 10240u;
        const uint32_t bh = base + 20480u, bl = base + 20480u + (uint32_t)BT;

#pragma unroll
        for (int ks = 0; ks < 2; ++ks) {
            uint32_t Ah[4][4], Al[4][4], Bh[4][2], Bl[4][2];
            const uint32_t ao = (uint32_t)(wm * 64 + (lane & 15)) * 80u
                              + (uint32_t)(ks * 16 + (lane >> 4) * 8) * 2u;
#pragma unroll
            for (int mi = 0; mi < 4; mi++) {
                ldsm4(Ah[mi], ah + ao + (uint32_t)(mi * 16) * 80u);
                ldsm4(Al[mi], al + ao + (uint32_t)(mi * 16) * 80u);
            }
            if (BKN) {
                const uint32_t brow = (uint32_t)(ks * 16 + (lane & 15));
#pragma unroll
                for (int p = 0; p < 2; p++) {
                    const uint32_t bo = brow * 272u
                        + (uint32_t)(wn * 32 + p * 16 + (lane >> 4) * 8) * 2u;
                    uint32_t r[4];
                    ldsm4t(r, bh + bo);
                    Bh[2*p][0] = r[0]; Bh[2*p][1] = r[1];
                    Bh[2*p+1][0] = r[2]; Bh[2*p+1][1] = r[3];
                    ldsm4t(r, bl + bo);
                    Bl[2*p][0] = r[0]; Bl[2*p][1] = r[1];
                    Bl[2*p+1][0] = r[2]; Bl[2*p+1][1] = r[3];
                }
            } else {
                const uint32_t bcol2 = (uint32_t)(ks * 16 + ((lane >> 3) & 1) * 8) * 2u;
#pragma unroll
                for (int p = 0; p < 2; p++) {
                    const uint32_t brow = (uint32_t)(wn * 32 + p * 16 + (lane & 7) + ((lane >> 4) << 3));
                    const uint32_t bo = brow * 80u + bcol2;
                    uint32_t r[4];
                    ldsm4(r, bh + bo);
                    Bh[2*p][0] = r[0]; Bh[2*p][1] = r[1];
                    Bh[2*p+1][0] = r[2]; Bh[2*p+1][1] = r[3];
                    ldsm4(r, bl + bo);
                    Bl[2*p][0] = r[0]; Bl[2*p][1] = r[1];
                    Bl[2*p+1][0] = r[2]; Bl[2*p+1][1] = r[3];
                }
            }
#pragma unroll
            for (int mi = 0; mi < 4; mi++)
#pragma unroll
                for (int ni = 0; ni < 4; ni++) {
                    mma_bf16(acc[mi][ni], Ah[mi], Bh[ni]);
                    mma_bf16(acc[mi][ni], Ah[mi], Bl[ni]);
                    mma_bf16(acc[mi][ni], Al[mi], Bh[ni]);
                }
        }
    }
    __syncthreads();
}

// ======================= 1-term fp16 GEMM: C = Ahi * Bhi, B in [k][n], 2-stage =======================
__device__ __forceinline__ void gemm1_f16(
    const __half* __restrict__ ahi, int lda,
    const __half* __restrict__ bhi, int ldb,
    int nchunks, float (&acc)[4][4][4])
{
    extern __shared__ char smem[];
    const uint32_t sb = smem_u32(smem);
    const int tid = threadIdx.x;
    const int lane = tid & 31, warp = tid >> 5;
    const int wm = warp >> 2, wn = warp & 3;

#pragma unroll
    for (int mi = 0; mi < 4; mi++)
#pragma unroll
        for (int ni = 0; ni < 4; ni++)
#pragma unroll
            for (int k = 0; k < 4; k++) acc[mi][ni][k] = 0.f;

    auto load_chunk = [&](int s, int c) {
        const uint32_t base = sb + (uint32_t)s * STAGE1_B;
        const uint32_t ah = base, bh = base + 10240u;
        int i = tid;
#pragma unroll
        for (int j = 0; j < 2; j++, i += 256) {
            {
                int row = i >> 2, cc = i & 3;
                size_t go = (size_t)row * lda + c * 32 + cc * 8;
                uint32_t so = (uint32_t)row * 80u + (uint32_t)cc * 16u;
                cp16(ah + so, ahi + go);
            }
            {
                int row = i >> 4, cc = i & 15;
                size_t go = (size_t)(c * 32 + row) * ldb + cc * 8;
                uint32_t so = (uint32_t)row * 272u + (uint32_t)cc * 16u;
                cp16(bh + so, bhi + go);
            }
        }
        cp_commit();
    };

    load_chunk(0, 0);
    for (int c = 0; c < nchunks; ++c) {
        cp_wait<0>();
        __syncthreads();
        if (c + 1 < nchunks) load_chunk((c + 1) & 1, c + 1);

        const int buf = c & 1;
        const uint32_t base = sb + (uint32_t)buf * STAGE1_B;
        const uint32_t ah = base, bh = base + 10240u;

#pragma unroll
        for (int ks = 0; ks < 2; ++ks) {
            uint32_t Ah[4][4], Bh[4][2];
            const uint32_t ao = (uint32_t)(wm * 64 + (lane & 15)) * 80u
                              + (uint32_t)(ks * 16 + (lane >> 4) * 8) * 2u;
#pragma unroll
            for (int mi = 0; mi < 4; mi++)
                ldsm4(Ah[mi], ah + ao + (uint32_t)(mi * 16) * 80u);
            const uint32_t brow = (uint32_t)(ks * 16 + (lane & 15));
#pragma unroll
            for (int p = 0; p < 2; p++) {
                const uint32_t bo = brow * 272u
                    + (uint32_t)(wn * 32 + p * 16 + (lane >> 4) * 8) * 2u;
                uint32_t r[4];
                ldsm4t(r, bh + bo);
                Bh[2*p][0] = r[0]; Bh[2*p][1] = r[1];
                Bh[2*p+1][0] = r[2]; Bh[2*p+1][1] = r[3];
            }
#pragma unroll
            for (int mi = 0; mi < 4; mi++)
#pragma unroll
                for (int ni = 0; ni < 4; ni++)
                    mma_f16(acc[mi][ni], Ah[mi], Bh[ni]);
        }
    }
    __syncthreads();
}

// ======================= kernel: split fp32 -> bf16 hi/lo (x + Wq + Wk + Wv) =======================
#define XN ((size_t)MTOT * DIM)          // 8388608
#define WN ((size_t)DIM * DIM)           // 1048576
__global__ __launch_bounds__(256) void split_all(const float* __restrict__ x,
                                                 const float* __restrict__ wq,
                                                 const float* __restrict__ wk,
                                                 const float* __restrict__ wv) {
    size_t i = ((size_t)blockIdx.x * 256 + threadIdx.x) * 4;
    const float* src;
    __nv_bfloat16 *hi, *lo;
    size_t off;
    if (i < XN) { src = x; off = i; hi = g_xhi; lo = g_xlo; }
    else {
        size_t j = i - XN;
        int w = (int)(j / WN);
        off = j - (size_t)w * WN;
        src = (w == 0) ? wq : (w == 1) ? wk : wv;
        hi = g_whi[w]; lo = g_wlo[w];
    }
    float4 v = *reinterpret_cast<const float4*>(src + off);
    float f[4] = {v.x, v.y, v.z, v.w};
    uint32_t hp[2], lp[2];
#pragma unroll
    for (int j = 0; j < 2; j++) {
        __nv_bfloat16 h0 = __float2bfloat16(f[2*j]),   h1 = __float2bfloat16(f[2*j+1]);
        __nv_bfloat16 l0 = __float2bfloat16(f[2*j]   - __bfloat162float(h0));
        __nv_bfloat16 l1 = __float2bfloat16(f[2*j+1] - __bfloat162float(h1));
        hp[j] = (uint32_t)__bfloat16_as_ushort(h0) | ((uint32_t)__bfloat16_as_ushort(h1) << 16);
        lp[j] = (uint32_t)__bfloat16_as_ushort(l0) | ((uint32_t)__bfloat16_as_ushort(l1) << 16);
    }
    *reinterpret_cast<uint2*>(hi + off) = make_uint2(hp[0], hp[1]);
    *reinterpret_cast<uint2*>(lo + off) = make_uint2(lp[0], lp[1]);
}

// ======================= kernel: QKV projection (128x128 tile, 256 threads) =======================
#define SMEM3Q_BYTES (2 * (20480 + 2 * 8704))    // 75776
__global__ __launch_bounds__(256) void qkv_gemm() {
    const int z = blockIdx.z, m0 = blockIdx.y * 128, n0 = blockIdx.x * 128;
    float acc[4][4][4];
    gemm3_bf16<true>(g_xhi + (size_t)m0 * DIM, g_xlo + (size_t)m0 * DIM, DIM,
                     g_whi[z] + n0, g_wlo[z] + n0, DIM, DIM / 32, acc);
    const int lane = threadIdx.x & 31, warp = threadIdx.x >> 5;
    const int g = lane >> 2, t = lane & 3, wm = warp >> 2, wn = warp & 3;
#pragma unroll
    for (int mi = 0; mi < 4; mi++) {
        const int r0 = m0 + wm * 64 + mi * 16 + g;
#pragma unroll
        for (int ni = 0; ni < 4; ni++) {
            const int cc = n0 + wn * 32 + ni * 8 + 2 * t;
            if (z == 2) {
                __half h0 = __float2half_rn(acc[mi][ni][0]);
                __half h1 = __float2half_rn(acc[mi][ni][1]);
                __half h2 = __float2half_rn(acc[mi][ni][2]);
                __half h3 = __float2half_rn(acc[mi][ni][3]);
                *reinterpret_cast<uint32_t*>(g_vh + (size_t)r0 * DIM + cc) =
                    (uint32_t)__half_as_ushort(h0) | ((uint32_t)__half_as_ushort(h1) << 16);
                *reinterpret_cast<uint32_t*>(g_vh + (size_t)(r0 + 8) * DIM + cc) =
                    (uint32_t)__half_as_ushort(h2) | ((uint32_t)__half_as_ushort(h3) << 16);
            } else {
                __nv_bfloat16* oh = (z == 0) ? g_qhi : g_khi;
                __nv_bfloat16* ol = (z == 0) ? g_qlo : g_klo;
                st_split2_bf16(oh, ol, (size_t)r0 * DIM + cc,       acc[mi][ni][0], acc[mi][ni][1]);
                st_split2_bf16(oh, ol, (size_t)(r0 + 8) * DIM + cc, acc[mi][ni][2], acc[mi][ni][3]);
            }
        }
    }
}

// ======================= kernel: fused scores = exp(QK^T*scale) (causal, triangular grid) =======================
#define SMEM3S_BYTES (2 * (20480 + 2 * 10240))   // 81920
__global__ __launch_bounds__(256) void scores_gemm() {
    extern __shared__ char smem[];
    // triangular decode: blockIdx.x in [0,136) -> (ty >= tx)
    const int li = blockIdx.x;
    int ty = (int)((sqrtf(8.f * li + 1.f) - 1.f) * 0.5f);
    while ((ty + 1) * (ty + 2) / 2 <= li) ty++;
    while (ty * (ty + 1) / 2 > li) ty--;
    const int tx = li - ty * (ty + 1) / 2;
    const int b = blockIdx.z, q0 = ty * 128, k0 = tx * 128;
    const size_t boff = (size_t)b * SEQ * DIM;
    float acc[4][4][4];
    gemm3_bf16<false>(g_qhi + boff + (size_t)q0 * DIM, g_qlo + boff + (size_t)q0 * DIM, DIM,
                      g_khi + boff + (size_t)k0 * DIM, g_klo + boff + (size_t)k0 * DIM, DIM,
                      DIM / 32, acc);
    const bool diag = (tx == ty);
    __half* ph = g_phi + (size_t)b * SEQ * SEQ;
    const int lane = threadIdx.x & 31, warp = threadIdx.x >> 5;
    const int g = lane >> 2, t = lane & 3, wm = warp >> 2, wn = warp & 3;
    const float scale = 0.03125f;

    float* red = reinterpret_cast<float*>(smem);
    float rs0[4], rs1[4];
#pragma unroll
    for (int mi = 0; mi < 4; mi++) { rs0[mi] = 0.f; rs1[mi] = 0.f; }

#pragma unroll
    for (int mi = 0; mi < 4; mi++) {
        const int r0 = q0 + wm * 64 + mi * 16 + g;
#pragma unroll
        for (int ni = 0; ni < 4; ni++) {
            const int cc = k0 + wn * 32 + ni * 8 + 2 * t;
            float e0 = __expf(acc[mi][ni][0] * scale);
            float e1 = __expf(acc[mi][ni][1] * scale);
            float e2 = __expf(acc[mi][ni][2] * scale);
            float e3 = __expf(acc[mi][ni][3] * scale);
            if (diag) {
                if (cc     > r0)     e0 = 0.f;
                if (cc + 1 > r0)     e1 = 0.f;
                if (cc     > r0 + 8) e2 = 0.f;
                if (cc + 1 > r0 + 8) e3 = 0.f;
            }
            __half p0 = __float2half_rn(e0), p1 = __float2half_rn(e1);
            __half p2 = __float2half_rn(e2), p3 = __float2half_rn(e3);
            *reinterpret_cast<uint32_t*>(ph + (size_t)r0 * SEQ + cc) =
                (uint32_t)__half_as_ushort(p0) | ((uint32_t)__half_as_ushort(p1) << 16);
            *reinterpret_cast<uint32_t*>(ph + (size_t)(r0 + 8) * SEQ + cc) =
                (uint32_t)__half_as_ushort(p2) | ((uint32_t)__half_as_ushort(p3) << 16);
            rs0[mi] += e0 + e1;
            rs1[mi] += e2 + e3;
        }
    }
#pragma unroll
    for (int mi = 0; mi < 4; mi++) {
        float s0 = rs0[mi], s1 = rs1[mi];
        s0 += __shfl_xor_sync(0xFFFFFFFFu, s0, 1);
        s0 += __shfl_xor_sync(0xFFFFFFFFu, s0, 2);
        s1 += __shfl_xor_sync(0xFFFFFFFFu, s1, 1);
        s1 += __shfl_xor_sync(0xFFFFFFFFu, s1, 2);
        if (t == 0) {
            const int lr = wm * 64 + mi * 16 + g;
            red[wn * 128 + lr]     = s0;
            red[wn * 128 + lr + 8] = s1;
        }
    }
    __syncthreads();
    if (threadIdx.x < 128) {
        float tot = red[threadIdx.x] + red[128 + threadIdx.x]
                  + red[256 + threadIdx.x] + red[384 + threadIdx.x];
        g_partial[b][tx][q0 + threadIdx.x] = tot;
    }
}

// ======================= kernel: O = (P @ V) * rsuminv (rowsum fused in prologue) =======================
__global__ __launch_bounds__(256) void pv_gemm(float* __restrict__ outp) {
    extern __shared__ char smem[];
    const int b = blockIdx.z, q0 = blockIdx.y * 128, n0 = blockIdx.x * 128;

    // prologue: per-row 1/rowsum into smem beyond the pipeline buffers
    float* rsinv = reinterpret_cast<float*>(smem + 2 * STAGE1_B);
    if (threadIdx.x < 128) {
        const int q = q0 + threadIdx.x;
        const int nt = (q0 >> 7) + 1;
        float s = 0.f;
        for (int j = 0; j < nt; j++) s += g_partial[b][j][q];
        rsinv[threadIdx.x] = 1.f / s;
    }

    float acc[4][4][4];
    gemm1_f16(g_phi + (size_t)b * SEQ * SEQ + (size_t)q0 * SEQ, SEQ,
              g_vh + (size_t)b * SEQ * DIM + n0, DIM,
              (q0 + 128) / 32, acc);   // ends with __syncthreads -> rsinv visible
    float* out = outp + (size_t)b * SEQ * DIM;
    const int lane = threadIdx.x & 31, warp = threadIdx.x >> 5;
    const int g = lane >> 2, t = lane & 3, wm = warp >> 2, wn = warp & 3;
#pragma unroll
    for (int mi = 0; mi < 4; mi++) {
        const int lr = wm * 64 + mi * 16 + g;
        const int r0 = q0 + lr;
        const float i0 = rsinv[lr], i1 = rsinv[lr + 8];
#pragma unroll
        for (int ni = 0; ni < 4; ni++) {
            const int cc = n0 + wn * 32 + ni * 8 + 2 * t;
            *reinterpret_cast<float2*>(out + (size_t)r0 * DIM + cc) =
                make_float2(acc[mi][ni][0] * i0, acc[mi][ni][1] * i0);
            *reinterpret_cast<float2*>(out + (size_t)(r0 + 8) * DIM + cc) =
                make_float2(acc[mi][ni][2] * i1, acc[mi][ni][3] * i1);
        }
    }
}

// ======================= launch =======================
extern "C" void kernel_launch(void* const* d_in, const int* in_sizes, int n_in,
                              void* d_out, int out_size) {
    const float* x  = (const float*)d_in[0];
    const float* Wq = (const float*)d_in[1];
    const float* Wk = (const float*)d_in[2];
    const float* Wv = (const float*)d_in[3];
    float* out = (float*)d_out;

    cudaFuncSetAttribute(qkv_gemm,    cudaFuncAttributeMaxDynamicSharedMemorySize, SMEM3Q_BYTES);
    cudaFuncSetAttribute(scores_gemm, cudaFuncAttributeMaxDynamicSharedMemorySize, SMEM3S_BYTES);
    cudaFuncSetAttribute(pv_gemm,     cudaFuncAttributeMaxDynamicSharedMemorySize, SMEM1_BYTES);

    const size_t total = XN + 3 * WN;
    split_all<<<(unsigned)(total / 1024), 256>>>(x, Wq, Wk, Wv);

    qkv_gemm<<<dim3(DIM / 128, MTOT / 128, 3), 256, SMEM3Q_BYTES>>>();
    scores_gemm<<<dim3(136, 1, BATCH), 256, SMEM3S_BYTES>>>();
    pv_gemm<<<dim3(DIM / 128, SEQ / 128, BATCH), 256, SMEM1_BYTES>>>(out);
}

// round 9
// speedup vs baseline: 1.0731x; 1.0515x over previous
#include <cuda_runtime.h>
#include <cuda_bf16.h>
#include <cuda_fp16.h>
#include <math.h>
#include <stdint.h>

#define BATCH 4
#define SEQ   2048
#define DIM   1024
#define MTOT  (BATCH * SEQ)   // 8192

// ======================= device scratch (no runtime alloc) =======================
__device__ __align__(128) __nv_bfloat16 g_xhi[(size_t)MTOT * DIM];
__device__ __align__(128) __nv_bfloat16 g_xlo[(size_t)MTOT * DIM];
__device__ __align__(128) __nv_bfloat16 g_whi[3][(size_t)DIM * DIM];   // [din][dout]
__device__ __align__(128) __nv_bfloat16 g_wlo[3][(size_t)DIM * DIM];
__device__ __align__(128) __nv_bfloat16 g_qhi[(size_t)MTOT * DIM];
__device__ __align__(128) __nv_bfloat16 g_qlo[(size_t)MTOT * DIM];
__device__ __align__(128) __nv_bfloat16 g_khi[(size_t)MTOT * DIM];
__device__ __align__(128) __nv_bfloat16 g_klo[(size_t)MTOT * DIM];
__device__ __align__(128) __half        g_vh[(size_t)MTOT * DIM];         // fp16 V
__device__ __align__(128) __half        g_phi[(size_t)BATCH * SEQ * SEQ]; // unnorm probs (fp16)
__device__ __align__(128) float         g_partial[BATCH][SEQ / 128][SEQ]; // rowsum partials

// ======================= PTX helpers (arch-agnostic, sm_80-era) =======================
__device__ __forceinline__ uint32_t smem_u32(const void* p) {
    uint32_t a;
    asm("{ .reg .u64 t; cvta.to.shared.u64 t, %1; cvt.u32.u64 %0, t; }" : "=r"(a) : "l"(p));
    return a;
}
__device__ __forceinline__ void cp16(uint32_t dst, const void* src) {
    asm volatile("cp.async.cg.shared.global [%0], [%1], 16;" :: "r"(dst), "l"(src));
}
__device__ __forceinline__ void cp_commit() { asm volatile("cp.async.commit_group;"); }
template<int N>
__device__ __forceinline__ void cp_wait() { asm volatile("cp.async.wait_group %0;" :: "n"(N)); }

__device__ __forceinline__ void ldsm4(uint32_t* r, uint32_t a) {
    asm volatile("ldmatrix.sync.aligned.m8n8.x4.shared.b16 {%0,%1,%2,%3}, [%4];"
                 : "=r"(r[0]), "=r"(r[1]), "=r"(r[2]), "=r"(r[3]) : "r"(a));
}
__device__ __forceinline__ void ldsm4t(uint32_t* r, uint32_t a) {
    asm volatile("ldmatrix.sync.aligned.m8n8.x4.trans.shared.b16 {%0,%1,%2,%3}, [%4];"
                 : "=r"(r[0]), "=r"(r[1]), "=r"(r[2]), "=r"(r[3]) : "r"(a));
}
__device__ __forceinline__ void mma_bf16(float* c, const uint32_t* a, const uint32_t* b) {
    asm volatile(
        "mma.sync.aligned.m16n8k16.row.col.f32.bf16.bf16.f32 "
        "{%0,%1,%2,%3},{%4,%5,%6,%7},{%8,%9},{%0,%1,%2,%3};"
        : "+f"(c[0]), "+f"(c[1]), "+f"(c[2]), "+f"(c[3])
        : "r"(a[0]), "r"(a[1]), "r"(a[2]), "r"(a[3]), "r"(b[0]), "r"(b[1]));
}
__device__ __forceinline__ void mma_f16(float* c, const uint32_t* a, const uint32_t* b) {
    asm volatile(
        "mma.sync.aligned.m16n8k16.row.col.f32.f16.f16.f32 "
        "{%0,%1,%2,%3},{%4,%5,%6,%7},{%8,%9},{%0,%1,%2,%3};"
        : "+f"(c[0]), "+f"(c[1]), "+f"(c[2]), "+f"(c[3])
        : "r"(a[0]), "r"(a[1]), "r"(a[2]), "r"(a[3]), "r"(b[0]), "r"(b[1]));
}

// ======================= smem layouts =======================
// gemm3 stage (128x128 tile): Ahi/Alo (128x32 halves, stride 80B = 10240B each)
//   + Bhi/Blo (BT each); BT = 8704 (KN) / 10240 (NK).
//   KN stage = 37888 -> 2 stages 75776 (2 CTAs/SM); NK stage = 40960 -> 81920 (2 CTAs/SM).
// pv (1-term) stage: Ahi(10240) + Bhi(8704) = 18944; 2 stages + 512B rsinv = 38400.
#define STAGE1_B    18944
#define SMEM1_BYTES (2 * STAGE1_B + 512)   // 38400

__device__ __forceinline__ void st_split2_bf16(__nv_bfloat16* hi, __nv_bfloat16* lo,
                                               size_t off, float f0, float f1) {
    __nv_bfloat16 h0 = __float2bfloat16(f0), h1 = __float2bfloat16(f1);
    __nv_bfloat16 l0 = __float2bfloat16(f0 - __bfloat162float(h0));
    __nv_bfloat16 l1 = __float2bfloat16(f1 - __bfloat162float(h1));
    uint32_t hp = (uint32_t)__bfloat16_as_ushort(h0) | ((uint32_t)__bfloat16_as_ushort(h1) << 16);
    uint32_t lp = (uint32_t)__bfloat16_as_ushort(l0) | ((uint32_t)__bfloat16_as_ushort(l1) << 16);
    *reinterpret_cast<uint32_t*>(hi + off) = hp;
    *reinterpret_cast<uint32_t*>(lo + off) = lp;
}

// ======================= 3-term split-bf16 GEMM (128x128 tile, 256 thr, 2-stage, 1 sync/chunk) =======================
// BKN=true : B stored [k][n] row-major (ldb = n-stride), uses ldmatrix.trans
// BKN=false: B stored [n][k] row-major (ldb = k-stride), uses ldmatrix
template<bool BKN>
__device__ __forceinline__ void gemm3_bf16(
    const __nv_bfloat16* __restrict__ ahi, const __nv_bfloat16* __restrict__ alo, int lda,
    const __nv_bfloat16* __restrict__ bhi, const __nv_bfloat16* __restrict__ blo, int ldb,
    int nchunks, float (&acc)[4][4][4])
{
    extern __shared__ char smem[];
    const uint32_t sb = smem_u32(smem);
    const int tid = threadIdx.x;
    const int lane = tid & 31, warp = tid >> 5;
    const int wm = warp >> 2, wn = warp & 3;
    constexpr int BT = BKN ? 8704 : 10240;
    constexpr int STAGE = 20480 + 2 * BT;

#pragma unroll
    for (int mi = 0; mi < 4; mi++)
#pragma unroll
        for (int ni = 0; ni < 4; ni++)
#pragma unroll
            for (int k = 0; k < 4; k++) acc[mi][ni][k] = 0.f;

    auto load_chunk = [&](int s, int c) {
        const uint32_t base = sb + (uint32_t)s * STAGE;
        const uint32_t ah = base, al = base + 10240u;
        const uint32_t bh = base + 20480u, bl = base + 20480u + (uint32_t)BT;
        int i = tid;
#pragma unroll
        for (int j = 0; j < 2; j++, i += 256) {
            {
                int row = i >> 2, cc = i & 3;
                size_t go = (size_t)row * lda + c * 32 + cc * 8;
                uint32_t so = (uint32_t)row * 80u + (uint32_t)cc * 16u;
                cp16(ah + so, ahi + go);
                cp16(al + so, alo + go);
            }
            if (BKN) {
                int row = i >> 4, cc = i & 15;
                size_t go = (size_t)(c * 32 + row) * ldb + cc * 8;
                uint32_t so = (uint32_t)row * 272u + (uint32_t)cc * 16u;
                cp16(bh + so, bhi + go);
                cp16(bl + so, blo + go);
            } else {
                int row = i >> 2, cc = i & 3;
                size_t go = (size_t)row * ldb + c * 32 + cc * 8;
                uint32_t so = (uint32_t)row * 80u + (uint32_t)cc * 16u;
                cp16(bh + so, bhi + go);
                cp16(bl + so, blo + go);
            }
        }
        cp_commit();
    };

    load_chunk(0, 0);
    for (int c = 0; c < nchunks; ++c) {
        cp_wait<0>();          // only chunk c's group outstanding
        __syncthreads();       // data visible + all warps done with chunk c-1
        if (c + 1 < nchunks) load_chunk((c + 1) & 1, c + 1);

        const int buf = c & 1;
        const uint32_t base = sb + (uint32_t)buf * STAGE;
        const uint32_t ah = base, al = base + 10240u;
        const uint32_t bh = base + 20480u, bl = base + 20480u + (uint32_t)BT;

#pragma unroll
        for (int ks = 0; ks < 2; ++ks) {
            uint32_t Ah[4][4], Al[4][4], Bh[4][2], Bl[4][2];
            const uint32_t ao = (uint32_t)(wm * 64 + (lane & 15)) * 80u
                              + (uint32_t)(ks * 16 + (lane >> 4) * 8) * 2u;
#pragma unroll
            for (int mi = 0; mi < 4; mi++) {
                ldsm4(Ah[mi], ah + ao + (uint32_t)(mi * 16) * 80u);
                ldsm4(Al[mi], al + ao + (uint32_t)(mi * 16) * 80u);
            }
            if (BKN) {
                const uint32_t brow = (uint32_t)(ks * 16 + (lane & 15));
#pragma unroll
                for (int p = 0; p < 2; p++) {
                    const uint32_t bo = brow * 272u
                        + (uint32_t)(wn * 32 + p * 16 + (lane >> 4) * 8) * 2u;
                    uint32_t r[4];
                    ldsm4t(r, bh + bo);
                    Bh[2*p][0] = r[0]; Bh[2*p][1] = r[1];
                    Bh[2*p+1][0] = r[2]; Bh[2*p+1][1] = r[3];
                    ldsm4t(r, bl + bo);
                    Bl[2*p][0] = r[0]; Bl[2*p][1] = r[1];
                    Bl[2*p+1][0] = r[2]; Bl[2*p+1][1] = r[3];
                }
            } else {
                const uint32_t bcol2 = (uint32_t)(ks * 16 + ((lane >> 3) & 1) * 8) * 2u;
#pragma unroll
                for (int p = 0; p < 2; p++) {
                    const uint32_t brow = (uint32_t)(wn * 32 + p * 16 + (lane & 7) + ((lane >> 4) << 3));
                    const uint32_t bo = brow * 80u + bcol2;
                    uint32_t r[4];
                    ldsm4(r, bh + bo);
                    Bh[2*p][0] = r[0]; Bh[2*p][1] = r[1];
                    Bh[2*p+1][0] = r[2]; Bh[2*p+1][1] = r[3];
                    ldsm4(r, bl + bo);
                    Bl[2*p][0] = r[0]; Bl[2*p][1] = r[1];
                    Bl[2*p+1][0] = r[2]; Bl[2*p+1][1] = r[3];
                }
            }
#pragma unroll
            for (int mi = 0; mi < 4; mi++)
#pragma unroll
                for (int ni = 0; ni < 4; ni++) {
                    mma_bf16(acc[mi][ni], Ah[mi], Bh[ni]);
                    mma_bf16(acc[mi][ni], Ah[mi], Bl[ni]);
                    mma_bf16(acc[mi][ni], Al[mi], Bh[ni]);
                }
        }
    }
    __syncthreads();
}

// ======================= 1-term fp16 GEMM: C = Ahi * Bhi, B in [k][n], 2-stage =======================
__device__ __forceinline__ void gemm1_f16(
    const __half* __restrict__ ahi, int lda,
    const __half* __restrict__ bhi, int ldb,
    int nchunks, float (&acc)[4][4][4])
{
    extern __shared__ char smem[];
    const uint32_t sb = smem_u32(smem);
    const int tid = threadIdx.x;
    const int lane = tid & 31, warp = tid >> 5;
    const int wm = warp >> 2, wn = warp & 3;

#pragma unroll
    for (int mi = 0; mi < 4; mi++)
#pragma unroll
        for (int ni = 0; ni < 4; ni++)
#pragma unroll
            for (int k = 0; k < 4; k++) acc[mi][ni][k] = 0.f;

    auto load_chunk = [&](int s, int c) {
        const uint32_t base = sb + (uint32_t)s * STAGE1_B;
        const uint32_t ah = base, bh = base + 10240u;
        int i = tid;
#pragma unroll
        for (int j = 0; j < 2; j++, i += 256) {
            {
                int row = i >> 2, cc = i & 3;
                size_t go = (size_t)row * lda + c * 32 + cc * 8;
                uint32_t so = (uint32_t)row * 80u + (uint32_t)cc * 16u;
                cp16(ah + so, ahi + go);
            }
            {
                int row = i >> 4, cc = i & 15;
                size_t go = (size_t)(c * 32 + row) * ldb + cc * 8;
                uint32_t so = (uint32_t)row * 272u + (uint32_t)cc * 16u;
                cp16(bh + so, bhi + go);
            }
        }
        cp_commit();
    };

    load_chunk(0, 0);
    for (int c = 0; c < nchunks; ++c) {
        cp_wait<0>();
        __syncthreads();
        if (c + 1 < nchunks) load_chunk((c + 1) & 1, c + 1);

        const int buf = c & 1;
        const uint32_t base = sb + (uint32_t)buf * STAGE1_B;
        const uint32_t ah = base, bh = base + 10240u;

#pragma unroll
        for (int ks = 0; ks < 2; ++ks) {
            uint32_t Ah[4][4], Bh[4][2];
            const uint32_t ao = (uint32_t)(wm * 64 + (lane & 15)) * 80u
                              + (uint32_t)(ks * 16 + (lane >> 4) * 8) * 2u;
#pragma unroll
            for (int mi = 0; mi < 4; mi++)
                ldsm4(Ah[mi], ah + ao + (uint32_t)(mi * 16) * 80u);
            const uint32_t brow = (uint32_t)(ks * 16 + (lane & 15));
#pragma unroll
            for (int p = 0; p < 2; p++) {
                const uint32_t bo = brow * 272u
                    + (uint32_t)(wn * 32 + p * 16 + (lane >> 4) * 8) * 2u;
                uint32_t r[4];
                ldsm4t(r, bh + bo);
                Bh[2*p][0] = r[0]; Bh[2*p][1] = r[1];
                Bh[2*p+1][0] = r[2]; Bh[2*p+1][1] = r[3];
            }
#pragma unroll
            for (int mi = 0; mi < 4; mi++)
#pragma unroll
                for (int ni = 0; ni < 4; ni++)
                    mma_f16(acc[mi][ni], Ah[mi], Bh[ni]);
        }
    }
    __syncthreads();
}

// ======================= kernel: split fp32 -> bf16 hi/lo (x + Wq + Wk + Wv) =======================
#define XN ((size_t)MTOT * DIM)          // 8388608
#define WN ((size_t)DIM * DIM)           // 1048576
__global__ __launch_bounds__(256) void split_all(const float* __restrict__ x,
                                                 const float* __restrict__ wq,
                                                 const float* __restrict__ wk,
                                                 const float* __restrict__ wv) {
    size_t i = ((size_t)blockIdx.x * 256 + threadIdx.x) * 4;
    const float* src;
    __nv_bfloat16 *hi, *lo;
    size_t off;
    if (i < XN) { src = x; off = i; hi = g_xhi; lo = g_xlo; }
    else {
        size_t j = i - XN;
        int w = (int)(j / WN);
        off = j - (size_t)w * WN;
        src = (w == 0) ? wq : (w == 1) ? wk : wv;
        hi = g_whi[w]; lo = g_wlo[w];
    }
    float4 v = *reinterpret_cast<const float4*>(src + off);
    float f[4] = {v.x, v.y, v.z, v.w};
    uint32_t hp[2], lp[2];
#pragma unroll
    for (int j = 0; j < 2; j++) {
        __nv_bfloat16 h0 = __float2bfloat16(f[2*j]),   h1 = __float2bfloat16(f[2*j+1]);
        __nv_bfloat16 l0 = __float2bfloat16(f[2*j]   - __bfloat162float(h0));
        __nv_bfloat16 l1 = __float2bfloat16(f[2*j+1] - __bfloat162float(h1));
        hp[j] = (uint32_t)__bfloat16_as_ushort(h0) | ((uint32_t)__bfloat16_as_ushort(h1) << 16);
        lp[j] = (uint32_t)__bfloat16_as_ushort(l0) | ((uint32_t)__bfloat16_as_ushort(l1) << 16);
    }
    *reinterpret_cast<uint2*>(hi + off) = make_uint2(hp[0], hp[1]);
    *reinterpret_cast<uint2*>(lo + off) = make_uint2(lp[0], lp[1]);
}

// ======================= kernel: QKV projection (128x128 tile, 256 threads) =======================
#define SMEM3Q_BYTES (2 * (20480 + 2 * 8704))    // 75776
__global__ __launch_bounds__(256) void qkv_gemm() {
    const int z = blockIdx.z, m0 = blockIdx.y * 128, n0 = blockIdx.x * 128;
    float acc[4][4][4];
    gemm3_bf16<true>(g_xhi + (size_t)m0 * DIM, g_xlo + (size_t)m0 * DIM, DIM,
                     g_whi[z] + n0, g_wlo[z] + n0, DIM, DIM / 32, acc);
    const int lane = threadIdx.x & 31, warp = threadIdx.x >> 5;
    const int g = lane >> 2, t = lane & 3, wm = warp >> 2, wn = warp & 3;
#pragma unroll
    for (int mi = 0; mi < 4; mi++) {
        const int r0 = m0 + wm * 64 + mi * 16 + g;
#pragma unroll
        for (int ni = 0; ni < 4; ni++) {
            const int cc = n0 + wn * 32 + ni * 8 + 2 * t;
            if (z == 2) {
                __half h0 = __float2half_rn(acc[mi][ni][0]);
                __half h1 = __float2half_rn(acc[mi][ni][1]);
                __half h2 = __float2half_rn(acc[mi][ni][2]);
                __half h3 = __float2half_rn(acc[mi][ni][3]);
                *reinterpret_cast<uint32_t*>(g_vh + (size_t)r0 * DIM + cc) =
                    (uint32_t)__half_as_ushort(h0) | ((uint32_t)__half_as_ushort(h1) << 16);
                *reinterpret_cast<uint32_t*>(g_vh + (size_t)(r0 + 8) * DIM + cc) =
                    (uint32_t)__half_as_ushort(h2) | ((uint32_t)__half_as_ushort(h3) << 16);
            } else {
                __nv_bfloat16* oh = (z == 0) ? g_qhi : g_khi;
                __nv_bfloat16* ol = (z == 0) ? g_qlo : g_klo;
                st_split2_bf16(oh, ol, (size_t)r0 * DIM + cc,       acc[mi][ni][0], acc[mi][ni][1]);
                st_split2_bf16(oh, ol, (size_t)(r0 + 8) * DIM + cc, acc[mi][ni][2], acc[mi][ni][3]);
            }
        }
    }
}

// ======================= kernel: fused scores = exp(QK^T*scale) (causal, rectangular grid) =======================
#define SMEM3S_BYTES (2 * (20480 + 2 * 10240))   // 81920
__global__ __launch_bounds__(256) void scores_gemm() {
    if (blockIdx.x > blockIdx.y) return;     // fully-masked tile, exits immediately
    extern __shared__ char smem[];
    const int b = blockIdx.z, q0 = blockIdx.y * 128, k0 = blockIdx.x * 128;
    const size_t boff = (size_t)b * SEQ * DIM;
    float acc[4][4][4];
    gemm3_bf16<false>(g_qhi + boff + (size_t)q0 * DIM, g_qlo + boff + (size_t)q0 * DIM, DIM,
                      g_khi + boff + (size_t)k0 * DIM, g_klo + boff + (size_t)k0 * DIM, DIM,
                      DIM / 32, acc);
    const bool diag = (blockIdx.x == blockIdx.y);
    __half* ph = g_phi + (size_t)b * SEQ * SEQ;
    const int lane = threadIdx.x & 31, warp = threadIdx.x >> 5;
    const int g = lane >> 2, t = lane & 3, wm = warp >> 2, wn = warp & 3;
    const float scale = 0.03125f;

    float* red = reinterpret_cast<float*>(smem);
    float rs0[4], rs1[4];
#pragma unroll
    for (int mi = 0; mi < 4; mi++) { rs0[mi] = 0.f; rs1[mi] = 0.f; }

#pragma unroll
    for (int mi = 0; mi < 4; mi++) {
        const int r0 = q0 + wm * 64 + mi * 16 + g;
#pragma unroll
        for (int ni = 0; ni < 4; ni++) {
            const int cc = k0 + wn * 32 + ni * 8 + 2 * t;
            float e0 = __expf(acc[mi][ni][0] * scale);
            float e1 = __expf(acc[mi][ni][1] * scale);
            float e2 = __expf(acc[mi][ni][2] * scale);
            float e3 = __expf(acc[mi][ni][3] * scale);
            if (diag) {
                if (cc     > r0)     e0 = 0.f;
                if (cc + 1 > r0)     e1 = 0.f;
                if (cc     > r0 + 8) e2 = 0.f;
                if (cc + 1 > r0 + 8) e3 = 0.f;
            }
            __half p0 = __float2half_rn(e0), p1 = __float2half_rn(e1);
            __half p2 = __float2half_rn(e2), p3 = __float2half_rn(e3);
            *reinterpret_cast<uint32_t*>(ph + (size_t)r0 * SEQ + cc) =
                (uint32_t)__half_as_ushort(p0) | ((uint32_t)__half_as_ushort(p1) << 16);
            *reinterpret_cast<uint32_t*>(ph + (size_t)(r0 + 8) * SEQ + cc) =
                (uint32_t)__half_as_ushort(p2) | ((uint32_t)__half_as_ushort(p3) << 16);
            rs0[mi] += e0 + e1;
            rs1[mi] += e2 + e3;
        }
    }
#pragma unroll
    for (int mi = 0; mi < 4; mi++) {
        float s0 = rs0[mi], s1 = rs1[mi];
        s0 += __shfl_xor_sync(0xFFFFFFFFu, s0, 1);
        s0 += __shfl_xor_sync(0xFFFFFFFFu, s0, 2);
        s1 += __shfl_xor_sync(0xFFFFFFFFu, s1, 1);
        s1 += __shfl_xor_sync(0xFFFFFFFFu, s1, 2);
        if (t == 0) {
            const int lr = wm * 64 + mi * 16 + g;
            red[wn * 128 + lr]     = s0;
            red[wn * 128 + lr + 8] = s1;
        }
    }
    __syncthreads();
    if (threadIdx.x < 128) {
        float tot = red[threadIdx.x] + red[128 + threadIdx.x]
                  + red[256 + threadIdx.x] + red[384 + threadIdx.x];
        g_partial[b][blockIdx.x][q0 + threadIdx.x] = tot;
    }
}

// ======================= kernel: O = (P @ V) * rsuminv (fused rowsum, heavy-first order) =======================
__global__ __launch_bounds__(256) void pv_gemm(float* __restrict__ outp) {
    extern __shared__ char smem[];
    const int b = blockIdx.z, n0 = blockIdx.x * 128;
    const int qy = (int)gridDim.y - 1 - (int)blockIdx.y;   // heavy q-tiles launch first
    const int q0 = qy * 128;

    // prologue: per-row 1/rowsum into smem beyond the pipeline buffers
    float* rsinv = reinterpret_cast<float*>(smem + 2 * STAGE1_B);
    if (threadIdx.x < 128) {
        const int q = q0 + threadIdx.x;
        const int nt = (q0 >> 7) + 1;
        float s = 0.f;
        for (int j = 0; j < nt; j++) s += g_partial[b][j][q];
        rsinv[threadIdx.x] = 1.f / s;
    }

    float acc[4][4][4];
    gemm1_f16(g_phi + (size_t)b * SEQ * SEQ + (size_t)q0 * SEQ, SEQ,
              g_vh + (size_t)b * SEQ * DIM + n0, DIM,
              (q0 + 128) / 32, acc);   // ends with __syncthreads -> rsinv visible
    float* out = outp + (size_t)b * SEQ * DIM;
    const int lane = threadIdx.x & 31, warp = threadIdx.x >> 5;
    const int g = lane >> 2, t = lane & 3, wm = warp >> 2, wn = warp & 3;
#pragma unroll
    for (int mi = 0; mi < 4; mi++) {
        const int lr = wm * 64 + mi * 16 + g;
        const int r0 = q0 + lr;
        const float i0 = rsinv[lr], i1 = rsinv[lr + 8];
#pragma unroll
        for (int ni = 0; ni < 4; ni++) {
            const int cc = n0 + wn * 32 + ni * 8 + 2 * t;
            *reinterpret_cast<float2*>(out + (size_t)r0 * DIM + cc) =
                make_float2(acc[mi][ni][0] * i0, acc[mi][ni][1] * i0);
            *reinterpret_cast<float2*>(out + (size_t)(r0 + 8) * DIM + cc) =
                make_float2(acc[mi][ni][2] * i1, acc[mi][ni][3] * i1);
        }
    }
}

// ======================= launch =======================
extern "C" void kernel_launch(void* const* d_in, const int* in_sizes, int n_in,
                              void* d_out, int out_size) {
    const float* x  = (const float*)d_in[0];
    const float* Wq = (const float*)d_in[1];
    const float* Wk = (const float*)d_in[2];
    const float* Wv = (const float*)d_in[3];
    float* out = (float*)d_out;

    cudaFuncSetAttribute(qkv_gemm,    cudaFuncAttributeMaxDynamicSharedMemorySize, SMEM3Q_BYTES);
    cudaFuncSetAttribute(scores_gemm, cudaFuncAttributeMaxDynamicSharedMemorySize, SMEM3S_BYTES);
    cudaFuncSetAttribute(pv_gemm,     cudaFuncAttributeMaxDynamicSharedMemorySize, SMEM1_BYTES);

    const size_t total = XN + 3 * WN;
    split_all<<<(unsigned)(total / 1024), 256>>>(x, Wq, Wk, Wv);

    qkv_gemm<<<dim3(DIM / 128, MTOT / 128, 3), 256, SMEM3Q_BYTES>>>();
    scores_gemm<<<dim3(SEQ / 128, SEQ / 128, BATCH), 256, SMEM3S_BYTES>>>();
    pv_gemm<<<dim3(DIM / 128, SEQ / 128, BATCH), 256, SMEM1_BYTES>>>(out);
}

// round 10
// speedup vs baseline: 1.0970x; 1.0223x over previous
#include <cuda_runtime.h>
#include <cuda_bf16.h>
#include <cuda_fp16.h>
#include <math.h>
#include <stdint.h>

#define BATCH 4
#define SEQ   2048
#define DIM   1024
#define MTOT  (BATCH * SEQ)   // 8192

// ======================= device scratch (no runtime alloc) =======================
__device__ __align__(128) __nv_bfloat16 g_xhi[(size_t)MTOT * DIM];
__device__ __align__(128) __nv_bfloat16 g_xlo[(size_t)MTOT * DIM];
__device__ __align__(128) __nv_bfloat16 g_whi[3][(size_t)DIM * DIM];   // [din][dout]
__device__ __align__(128) __nv_bfloat16 g_wlo[3][(size_t)DIM * DIM];
__device__ __align__(128) __nv_bfloat16 g_qhi[(size_t)MTOT * DIM];
__device__ __align__(128) __nv_bfloat16 g_qlo[(size_t)MTOT * DIM];
__device__ __align__(128) __nv_bfloat16 g_khi[(size_t)MTOT * DIM];
__device__ __align__(128) __nv_bfloat16 g_klo[(size_t)MTOT * DIM];
__device__ __align__(128) __half        g_vh[(size_t)MTOT * DIM];         // fp16 V
__device__ __align__(128) __half        g_phi[(size_t)BATCH * SEQ * SEQ]; // unnorm probs (fp16)
__device__ __align__(128) float         g_partial[BATCH][SEQ / 128][SEQ]; // rowsum partials

// ======================= PTX helpers (arch-agnostic, sm_80-era) =======================
__device__ __forceinline__ uint32_t smem_u32(const void* p) {
    uint32_t a;
    asm("{ .reg .u64 t; cvta.to.shared.u64 t, %1; cvt.u32.u64 %0, t; }" : "=r"(a) : "l"(p));
    return a;
}
__device__ __forceinline__ void cp16(uint32_t dst, const void* src) {
    asm volatile("cp.async.cg.shared.global [%0], [%1], 16;" :: "r"(dst), "l"(src));
}
__device__ __forceinline__ void cp_commit() { asm volatile("cp.async.commit_group;"); }
template<int N>
__device__ __forceinline__ void cp_wait() { asm volatile("cp.async.wait_group %0;" :: "n"(N)); }
template<int NSTAGES>
__device__ __forceinline__ void cp_wait_stage() {
    if constexpr (NSTAGES == 2)      cp_wait<0>();
    else if constexpr (NSTAGES == 3) cp_wait<1>();
    else                             cp_wait<2>();
}

__device__ __forceinline__ void ldsm4(uint32_t* r, uint32_t a) {
    asm volatile("ldmatrix.sync.aligned.m8n8.x4.shared.b16 {%0,%1,%2,%3}, [%4];"
                 : "=r"(r[0]), "=r"(r[1]), "=r"(r[2]), "=r"(r[3]) : "r"(a));
}
__device__ __forceinline__ void ldsm4t(uint32_t* r, uint32_t a) {
    asm volatile("ldmatrix.sync.aligned.m8n8.x4.trans.shared.b16 {%0,%1,%2,%3}, [%4];"
                 : "=r"(r[0]), "=r"(r[1]), "=r"(r[2]), "=r"(r[3]) : "r"(a));
}
__device__ __forceinline__ void mma_bf16(float* c, const uint32_t* a, const uint32_t* b) {
    asm volatile(
        "mma.sync.aligned.m16n8k16.row.col.f32.bf16.bf16.f32 "
        "{%0,%1,%2,%3},{%4,%5,%6,%7},{%8,%9},{%0,%1,%2,%3};"
        : "+f"(c[0]), "+f"(c[1]), "+f"(c[2]), "+f"(c[3])
        : "r"(a[0]), "r"(a[1]), "r"(a[2]), "r"(a[3]), "r"(b[0]), "r"(b[1]));
}
__device__ __forceinline__ void mma_f16(float* c, const uint32_t* a, const uint32_t* b) {
    asm volatile(
        "mma.sync.aligned.m16n8k16.row.col.f32.f16.f16.f32 "
        "{%0,%1,%2,%3},{%4,%5,%6,%7},{%8,%9},{%0,%1,%2,%3};"
        : "+f"(c[0]), "+f"(c[1]), "+f"(c[2]), "+f"(c[3])
        : "r"(a[0]), "r"(a[1]), "r"(a[2]), "r"(a[3]), "r"(b[0]), "r"(b[1]));
}

// ======================= smem layouts =======================
// gemm3 stage (128x128 tile): Ahi/Alo (10240B each) + Bhi/Blo (BT each);
//   BT = 8704 (KN) / 10240 (NK). KN stage 37888; NK stage 40960.
// qkv:    3 stages x 37888 = 113664  (2 CTAs/SM: 227328 <= 228KB)
// scores: 2 stages x 40960 = 81920   (2 CTAs/SM)
// pv:     4 stages x 18944 + 512 = 76288 (2+ CTAs/SM)
#define STAGE1_B    18944
#define PV_STAGES   4
#define SMEM1_BYTES (PV_STAGES * STAGE1_B + 512)   // 76288

__device__ __forceinline__ void st_split2_bf16(__nv_bfloat16* hi, __nv_bfloat16* lo,
                                               size_t off, float f0, float f1) {
    __nv_bfloat16 h0 = __float2bfloat16(f0), h1 = __float2bfloat16(f1);
    __nv_bfloat16 l0 = __float2bfloat16(f0 - __bfloat162float(h0));
    __nv_bfloat16 l1 = __float2bfloat16(f1 - __bfloat162float(h1));
    uint32_t hp = (uint32_t)__bfloat16_as_ushort(h0) | ((uint32_t)__bfloat16_as_ushort(h1) << 16);
    uint32_t lp = (uint32_t)__bfloat16_as_ushort(l0) | ((uint32_t)__bfloat16_as_ushort(l1) << 16);
    *reinterpret_cast<uint32_t*>(hi + off) = hp;
    *reinterpret_cast<uint32_t*>(lo + off) = lp;
}

// ======================= 3-term split-bf16 GEMM (128x128 tile, 256 thr, NSTAGES, 1 sync/chunk) =======================
// Per-iteration group accounting: exactly ONE commit_group per iteration (empty when no load
// remains), so wait_group<NSTAGES-2> always certifies chunk c's group complete, incl. loop tail.
template<bool BKN, int NSTAGES>
__device__ __forceinline__ void gemm3_bf16(
    const __nv_bfloat16* __restrict__ ahi, const __nv_bfloat16* __restrict__ alo, int lda,
    const __nv_bfloat16* __restrict__ bhi, const __nv_bfloat16* __restrict__ blo, int ldb,
    int nchunks, float (&acc)[4][4][4])
{
    extern __shared__ char smem[];
    const uint32_t sb = smem_u32(smem);
    const int tid = threadIdx.x;
    const int lane = tid & 31, warp = tid >> 5;
    const int wm = warp >> 2, wn = warp & 3;
    constexpr int BT = BKN ? 8704 : 10240;
    constexpr int STAGE = 20480 + 2 * BT;

#pragma unroll
    for (int mi = 0; mi < 4; mi++)
#pragma unroll
        for (int ni = 0; ni < 4; ni++)
#pragma unroll
            for (int k = 0; k < 4; k++) acc[mi][ni][k] = 0.f;

    auto load_chunk = [&](int s, int c) {
        const uint32_t base = sb + (uint32_t)s * STAGE;
        const uint32_t ah = base, al = base + 10240u;
        const uint32_t bh = base + 20480u, bl = base + 20480u + (uint32_t)BT;
        int i = tid;
#pragma unroll
        for (int j = 0; j < 2; j++, i += 256) {
            {
                int row = i >> 2, cc = i & 3;
                size_t go = (size_t)row * lda + c * 32 + cc * 8;
                uint32_t so = (uint32_t)row * 80u + (uint32_t)cc * 16u;
                cp16(ah + so, ahi + go);
                cp16(al + so, alo + go);
            }
            if (BKN) {
                int row = i >> 4, cc = i & 15;
                size_t go = (size_t)(c * 32 + row) * ldb + cc * 8;
                uint32_t so = (uint32_t)row * 272u + (uint32_t)cc * 16u;
                cp16(bh + so, bhi + go);
                cp16(bl + so, blo + go);
            } else {
                int row = i >> 2, cc = i & 3;
                size_t go = (size_t)row * ldb + c * 32 + cc * 8;
                uint32_t so = (uint32_t)row * 80u + (uint32_t)cc * 16u;
                cp16(bh + so, bhi + go);
                cp16(bl + so, blo + go);
            }
        }
        cp_commit();
    };

    // prologue: chunks 0 .. NSTAGES-2 (one group each)
#pragma unroll
    for (int s = 0; s < NSTAGES - 1; s++)
        if (s < nchunks) load_chunk(s, s);

    for (int c = 0; c < nchunks; ++c) {
        cp_wait_stage<NSTAGES>();   // chunk c's group certified complete
        __syncthreads();            // + all warps done computing chunk c-NSTAGES+1's slot
        const int cnext = c + NSTAGES - 1;
        if (cnext < nchunks) {
            int s = cnext; while (s >= NSTAGES) s -= NSTAGES;
            load_chunk(s, cnext);
        } else {
            cp_commit();            // empty group keeps wait<k> accounting exact at the tail
        }

        int s = c; while (s >= NSTAGES) s -= NSTAGES;
        const uint32_t base = sb + (uint32_t)s * STAGE;
        const uint32_t ah = base, al = base + 10240u;
        const uint32_t bh = base + 20480u, bl = base + 20480u + (uint32_t)BT;

#pragma unroll
        for (int ks = 0; ks < 2; ++ks) {
            uint32_t Ah[4][4], Al[4][4], Bh[4][2], Bl[4][2];
            const uint32_t ao = (uint32_t)(wm * 64 + (lane & 15)) * 80u
                              + (uint32_t)(ks * 16 + (lane >> 4) * 8) * 2u;
#pragma unroll
            for (int mi = 0; mi < 4; mi++) {
                ldsm4(Ah[mi], ah + ao + (uint32_t)(mi * 16) * 80u);
                ldsm4(Al[mi], al + ao + (uint32_t)(mi * 16) * 80u);
            }
            if (BKN) {
                const uint32_t brow = (uint32_t)(ks * 16 + (lane & 15));
#pragma unroll
                for (int p = 0; p < 2; p++) {
                    const uint32_t bo = brow * 272u
                        + (uint32_t)(wn * 32 + p * 16 + (lane >> 4) * 8) * 2u;
                    uint32_t r[4];
                    ldsm4t(r, bh + bo);
                    Bh[2*p][0] = r[0]; Bh[2*p][1] = r[1];
                    Bh[2*p+1][0] = r[2]; Bh[2*p+1][1] = r[3];
                    ldsm4t(r, bl + bo);
                    Bl[2*p][0] = r[0]; Bl[2*p][1] = r[1];
                    Bl[2*p+1][0] = r[2]; Bl[2*p+1][1] = r[3];
                }
            } else {
                const uint32_t bcol2 = (uint32_t)(ks * 16 + ((lane >> 3) & 1) * 8) * 2u;
#pragma unroll
                for (int p = 0; p < 2; p++) {
                    const uint32_t brow = (uint32_t)(wn * 32 + p * 16 + (lane & 7) + ((lane >> 4) << 3));
                    const uint32_t bo = brow * 80u + bcol2;
                    uint32_t r[4];
                    ldsm4(r, bh + bo);
                    Bh[2*p][0] = r[0]; Bh[2*p][1] = r[1];
                    Bh[2*p+1][0] = r[2]; Bh[2*p+1][1] = r[3];
                    ldsm4(r, bl + bo);
                    Bl[2*p][0] = r[0]; Bl[2*p][1] = r[1];
                    Bl[2*p+1][0] = r[2]; Bl[2*p+1][1] = r[3];
                }
            }
#pragma unroll
            for (int mi = 0; mi < 4; mi++)
#pragma unroll
                for (int ni = 0; ni < 4; ni++) {
                    mma_bf16(acc[mi][ni], Ah[mi], Bh[ni]);
                    mma_bf16(acc[mi][ni], Ah[mi], Bl[ni]);
                    mma_bf16(acc[mi][ni], Al[mi], Bh[ni]);
                }
        }
    }
    __syncthreads();
}

// ======================= 1-term fp16 GEMM: C = Ahi * Bhi, B in [k][n], PV_STAGES deep =======================
__device__ __forceinline__ void gemm1_f16(
    const __half* __restrict__ ahi, int lda,
    const __half* __restrict__ bhi, int ldb,
    int nchunks, float (&acc)[4][4][4])
{
    extern __shared__ char smem[];
    const uint32_t sb = smem_u32(smem);
    const int tid = threadIdx.x;
    const int lane = tid & 31, warp = tid >> 5;
    const int wm = warp >> 2, wn = warp & 3;

#pragma unroll
    for (int mi = 0; mi < 4; mi++)
#pragma unroll
        for (int ni = 0; ni < 4; ni++)
#pragma unroll
            for (int k = 0; k < 4; k++) acc[mi][ni][k] = 0.f;

    auto load_chunk = [&](int s, int c) {
        const uint32_t base = sb + (uint32_t)s * STAGE1_B;
        const uint32_t ah = base, bh = base + 10240u;
        int i = tid;
#pragma unroll
        for (int j = 0; j < 2; j++, i += 256) {
            {
                int row = i >> 2, cc = i & 3;
                size_t go = (size_t)row * lda + c * 32 + cc * 8;
                uint32_t so = (uint32_t)row * 80u + (uint32_t)cc * 16u;
                cp16(ah + so, ahi + go);
            }
            {
                int row = i >> 4, cc = i & 15;
                size_t go = (size_t)(c * 32 + row) * ldb + cc * 8;
                uint32_t so = (uint32_t)row * 272u + (uint32_t)cc * 16u;
                cp16(bh + so, bhi + go);
            }
        }
        cp_commit();
    };

#pragma unroll
    for (int s = 0; s < PV_STAGES - 1; s++)
        if (s < nchunks) load_chunk(s, s);

    for (int c = 0; c < nchunks; ++c) {
        cp_wait_stage<PV_STAGES>();
        __syncthreads();
        const int cnext = c + PV_STAGES - 1;
        if (cnext < nchunks) {
            int s = cnext; while (s >= PV_STAGES) s -= PV_STAGES;
            load_chunk(s, cnext);
        } else {
            cp_commit();
        }

        int s = c; while (s >= PV_STAGES) s -= PV_STAGES;
        const uint32_t base = sb + (uint32_t)s * STAGE1_B;
        const uint32_t ah = base, bh = base + 10240u;

#pragma unroll
        for (int ks = 0; ks < 2; ++ks) {
            uint32_t Ah[4][4], Bh[4][2];
            const uint32_t ao = (uint32_t)(wm * 64 + (lane & 15)) * 80u
                              + (uint32_t)(ks * 16 + (lane >> 4) * 8) * 2u;
#pragma unroll
            for (int mi = 0; mi < 4; mi++)
                ldsm4(Ah[mi], ah + ao + (uint32_t)(mi * 16) * 80u);
            const uint32_t brow = (uint32_t)(ks * 16 + (lane & 15));
#pragma unroll
            for (int p = 0; p < 2; p++) {
                const uint32_t bo = brow * 272u
                    + (uint32_t)(wn * 32 + p * 16 + (lane >> 4) * 8) * 2u;
                uint32_t r[4];
                ldsm4t(r, bh + bo);
                Bh[2*p][0] = r[0]; Bh[2*p][1] = r[1];
                Bh[2*p+1][0] = r[2]; Bh[2*p+1][1] = r[3];
            }
#pragma unroll
            for (int mi = 0; mi < 4; mi++)
#pragma unroll
                for (int ni = 0; ni < 4; ni++)
                    mma_f16(acc[mi][ni], Ah[mi], Bh[ni]);
        }
    }
    __syncthreads();
}

// ======================= kernel: split fp32 -> bf16 hi/lo (x + Wq + Wk + Wv) =======================
#define XN ((size_t)MTOT * DIM)          // 8388608
#define WN ((size_t)DIM * DIM)           // 1048576
__global__ __launch_bounds__(256) void split_all(const float* __restrict__ x,
                                                 const float* __restrict__ wq,
                                                 const float* __restrict__ wk,
                                                 const float* __restrict__ wv) {
    size_t i = ((size_t)blockIdx.x * 256 + threadIdx.x) * 4;
    const float* src;
    __nv_bfloat16 *hi, *lo;
    size_t off;
    if (i < XN) { src = x; off = i; hi = g_xhi; lo = g_xlo; }
    else {
        size_t j = i - XN;
        int w = (int)(j / WN);
        off = j - (size_t)w * WN;
        src = (w == 0) ? wq : (w == 1) ? wk : wv;
        hi = g_whi[w]; lo = g_wlo[w];
    }
    float4 v = *reinterpret_cast<const float4*>(src + off);
    float f[4] = {v.x, v.y, v.z, v.w};
    uint32_t hp[2], lp[2];
#pragma unroll
    for (int j = 0; j < 2; j++) {
        __nv_bfloat16 h0 = __float2bfloat16(f[2*j]),   h1 = __float2bfloat16(f[2*j+1]);
        __nv_bfloat16 l0 = __float2bfloat16(f[2*j]   - __bfloat162float(h0));
        __nv_bfloat16 l1 = __float2bfloat16(f[2*j+1] - __bfloat162float(h1));
        hp[j] = (uint32_t)__bfloat16_as_ushort(h0) | ((uint32_t)__bfloat16_as_ushort(h1) << 16);
        lp[j] = (uint32_t)__bfloat16_as_ushort(l0) | ((uint32_t)__bfloat16_as_ushort(l1) << 16);
    }
    *reinterpret_cast<uint2*>(hi + off) = make_uint2(hp[0], hp[1]);
    *reinterpret_cast<uint2*>(lo + off) = make_uint2(lp[0], lp[1]);
}

// ======================= kernel: QKV projection (128x128 tile, 256 threads, 3-stage) =======================
#define SMEM3Q_BYTES (3 * (20480 + 2 * 8704))    // 113664
__global__ __launch_bounds__(256) void qkv_gemm() {
    const int z = blockIdx.z, m0 = blockIdx.y * 128, n0 = blockIdx.x * 128;
    float acc[4][4][4];
    gemm3_bf16<true, 3>(g_xhi + (size_t)m0 * DIM, g_xlo + (size_t)m0 * DIM, DIM,
                        g_whi[z] + n0, g_wlo[z] + n0, DIM, DIM / 32, acc);
    const int lane = threadIdx.x & 31, warp = threadIdx.x >> 5;
    const int g = lane >> 2, t = lane & 3, wm = warp >> 2, wn = warp & 3;
#pragma unroll
    for (int mi = 0; mi < 4; mi++) {
        const int r0 = m0 + wm * 64 + mi * 16 + g;
#pragma unroll
        for (int ni = 0; ni < 4; ni++) {
            const int cc = n0 + wn * 32 + ni * 8 + 2 * t;
            if (z == 2) {
                __half h0 = __float2half_rn(acc[mi][ni][0]);
                __half h1 = __float2half_rn(acc[mi][ni][1]);
                __half h2 = __float2half_rn(acc[mi][ni][2]);
                __half h3 = __float2half_rn(acc[mi][ni][3]);
                *reinterpret_cast<uint32_t*>(g_vh + (size_t)r0 * DIM + cc) =
                    (uint32_t)__half_as_ushort(h0) | ((uint32_t)__half_as_ushort(h1) << 16);
                *reinterpret_cast<uint32_t*>(g_vh + (size_t)(r0 + 8) * DIM + cc) =
                    (uint32_t)__half_as_ushort(h2) | ((uint32_t)__half_as_ushort(h3) << 16);
            } else {
                __nv_bfloat16* oh = (z == 0) ? g_qhi : g_khi;
                __nv_bfloat16* ol = (z == 0) ? g_qlo : g_klo;
                st_split2_bf16(oh, ol, (size_t)r0 * DIM + cc,       acc[mi][ni][0], acc[mi][ni][1]);
                st_split2_bf16(oh, ol, (size_t)(r0 + 8) * DIM + cc, acc[mi][ni][2], acc[mi][ni][3]);
            }
        }
    }
}

// ======================= kernel: fused scores = exp(QK^T*scale) (causal, rectangular grid, 2-stage) =======================
#define SMEM3S_BYTES (2 * (20480 + 2 * 10240))   // 81920
__global__ __launch_bounds__(256) void scores_gemm() {
    if (blockIdx.x > blockIdx.y) return;     // fully-masked tile, exits immediately
    extern __shared__ char smem[];
    const int b = blockIdx.z, q0 = blockIdx.y * 128, k0 = blockIdx.x * 128;
    const size_t boff = (size_t)b * SEQ * DIM;
    float acc[4][4][4];
    gemm3_bf16<false, 2>(g_qhi + boff + (size_t)q0 * DIM, g_qlo + boff + (size_t)q0 * DIM, DIM,
                         g_khi + boff + (size_t)k0 * DIM, g_klo + boff + (size_t)k0 * DIM, DIM,
                         DIM / 32, acc);
    const bool diag = (blockIdx.x == blockIdx.y);
    __half* ph = g_phi + (size_t)b * SEQ * SEQ;
    const int lane = threadIdx.x & 31, warp = threadIdx.x >> 5;
    const int g = lane >> 2, t = lane & 3, wm = warp >> 2, wn = warp & 3;
    const float scale = 0.03125f;

    float* red = reinterpret_cast<float*>(smem);
    float rs0[4], rs1[4];
#pragma unroll
    for (int mi = 0; mi < 4; mi++) { rs0[mi] = 0.f; rs1[mi] = 0.f; }

#pragma unroll
    for (int mi = 0; mi < 4; mi++) {
        const int r0 = q0 + wm * 64 + mi * 16 + g;
#pragma unroll
        for (int ni = 0; ni < 4; ni++) {
            const int cc = k0 + wn * 32 + ni * 8 + 2 * t;
            float e0 = __expf(acc[mi][ni][0] * scale);
            float e1 = __expf(acc[mi][ni][1] * scale);
            float e2 = __expf(acc[mi][ni][2] * scale);
            float e3 = __expf(acc[mi][ni][3] * scale);
            if (diag) {
                if (cc     > r0)     e0 = 0.f;
                if (cc + 1 > r0)     e1 = 0.f;
                if (cc     > r0 + 8) e2 = 0.f;
                if (cc + 1 > r0 + 8) e3 = 0.f;
            }
            __half p0 = __float2half_rn(e0), p1 = __float2half_rn(e1);
            __half p2 = __float2half_rn(e2), p3 = __float2half_rn(e3);
            *reinterpret_cast<uint32_t*>(ph + (size_t)r0 * SEQ + cc) =
                (uint32_t)__half_as_ushort(p0) | ((uint32_t)__half_as_ushort(p1) << 16);
            *reinterpret_cast<uint32_t*>(ph + (size_t)(r0 + 8) * SEQ + cc) =
                (uint32_t)__half_as_ushort(p2) | ((uint32_t)__half_as_ushort(p3) << 16);
            rs0[mi] += e0 + e1;
            rs1[mi] += e2 + e3;
        }
    }
#pragma unroll
    for (int mi = 0; mi < 4; mi++) {
        float s0 = rs0[mi], s1 = rs1[mi];
        s0 += __shfl_xor_sync(0xFFFFFFFFu, s0, 1);
        s0 += __shfl_xor_sync(0xFFFFFFFFu, s0, 2);
        s1 += __shfl_xor_sync(0xFFFFFFFFu, s1, 1);
        s1 += __shfl_xor_sync(0xFFFFFFFFu, s1, 2);
        if (t == 0) {
            const int lr = wm * 64 + mi * 16 + g;
            red[wn * 128 + lr]     = s0;
            red[wn * 128 + lr + 8] = s1;
        }
    }
    __syncthreads();
    if (threadIdx.x < 128) {
        float tot = red[threadIdx.x] + red[128 + threadIdx.x]
                  + red[256 + threadIdx.x] + red[384 + threadIdx.x];
        g_partial[b][blockIdx.x][q0 + threadIdx.x] = tot;
    }
}

// ======================= kernel: O = (P @ V) * rsuminv (fused rowsum, heavy-first order) =======================
__global__ __launch_bounds__(256) void pv_gemm(float* __restrict__ outp) {
    extern __shared__ char smem[];
    const int b = blockIdx.z, n0 = blockIdx.x * 128;
    const int qy = (int)gridDim.y - 1 - (int)blockIdx.y;   // heavy q-tiles launch first
    const int q0 = qy * 128;

    // prologue: per-row 1/rowsum into smem beyond the pipeline buffers
    float* rsinv = reinterpret_cast<float*>(smem + PV_STAGES * STAGE1_B);
    if (threadIdx.x < 128) {
        const int q = q0 + threadIdx.x;
        const int nt = (q0 >> 7) + 1;
        float s = 0.f;
        for (int j = 0; j < nt; j++) s += g_partial[b][j][q];
        rsinv[threadIdx.x] = 1.f / s;
    }

    float acc[4][4][4];
    gemm1_f16(g_phi + (size_t)b * SEQ * SEQ + (size_t)q0 * SEQ, SEQ,
              g_vh + (size_t)b * SEQ * DIM + n0, DIM,
              (q0 + 128) / 32, acc);   // ends with __syncthreads -> rsinv visible
    float* out = outp + (size_t)b * SEQ * DIM;
    const int lane = threadIdx.x & 31, warp = threadIdx.x >> 5;
    const int g = lane >> 2, t = lane & 3, wm = warp >> 2, wn = warp & 3;
#pragma unroll
    for (int mi = 0; mi < 4; mi++) {
        const int lr = wm * 64 + mi * 16 + g;
        const int r0 = q0 + lr;
        const float i0 = rsinv[lr], i1 = rsinv[lr + 8];
#pragma unroll
        for (int ni = 0; ni < 4; ni++) {
            const int cc = n0 + wn * 32 + ni * 8 + 2 * t;
            *reinterpret_cast<float2*>(out + (size_t)r0 * DIM + cc) =
                make_float2(acc[mi][ni][0] * i0, acc[mi][ni][1] * i0);
            *reinterpret_cast<float2*>(out + (size_t)(r0 + 8) * DIM + cc) =
                make_float2(acc[mi][ni][2] * i1, acc[mi][ni][3] * i1);
        }
    }
}

// ======================= launch =======================
extern "C" void kernel_launch(void* const* d_in, const int* in_sizes, int n_in,
                              void* d_out, int out_size) {
    const float* x  = (const float*)d_in[0];
    const float* Wq = (const float*)d_in[1];
    const float* Wk = (const float*)d_in[2];
    const float* Wv = (const float*)d_in[3];
    float* out = (float*)d_out;

    cudaFuncSetAttribute(qkv_gemm,    cudaFuncAttributeMaxDynamicSharedMemorySize, SMEM3Q_BYTES);
    cudaFuncSetAttribute(scores_gemm, cudaFuncAttributeMaxDynamicSharedMemorySize, SMEM3S_BYTES);
    cudaFuncSetAttribute(pv_gemm,     cudaFuncAttributeMaxDynamicSharedMemorySize, SMEM1_BYTES);

    const size_t total = XN + 3 * WN;
    split_all<<<(unsigned)(total / 1024), 256>>>(x, Wq, Wk, Wv);

    qkv_gemm<<<dim3(DIM / 128, MTOT / 128, 3), 256, SMEM3Q_BYTES>>>();
    scores_gemm<<<dim3(SEQ / 128, SEQ / 128, BATCH), 256, SMEM3S_BYTES>>>();
    pv_gemm<<<dim3(DIM / 128, SEQ / 128, BATCH), 256, SMEM1_BYTES>>>(out);
}